// round 6
// baseline (speedup 1.0000x reference)
#include <cuda_runtime.h>
#include <cuda_bf16.h>
#include <math.h>
#include <stdint.h>

// Problem constants
constexpr int B_ = 4;
constexpr int T_ = 2048;
constexpr int D_ = 1024;
constexpr int H_ = 16;
constexpr int DK_ = 64;
constexpr int M_ = B_ * T_;   // 8192
constexpr int N_ = D_;        // 1024
constexpr int K_ = D_;        // 1024

// bf16 split arenas (hi + lo). Layout: [x (M*K)][W0..W3 (4*N*K)][attn-out (M*D)]
constexpr size_t XOFF = 0;
constexpr size_t WOFF = (size_t)M_ * K_;
constexpr size_t AOFF = WOFF + 4ull * N_ * K_;
constexpr size_t ARENA = AOFF + (size_t)M_ * D_;

__device__ __nv_bfloat16 g_hi[ARENA];
__device__ __nv_bfloat16 g_lo[ARENA];

// Q/K/V in bf16 hi/lo, layout [B*H, T, DK]
constexpr size_t QKV_SZ = (size_t)B_ * H_ * T_ * DK_;
__device__ __nv_bfloat16 g_qh[QKV_SZ], g_ql[QKV_SZ];
__device__ __nv_bfloat16 g_kh[QKV_SZ], g_kl[QKV_SZ];
__device__ __nv_bfloat16 g_vh[QKV_SZ], g_vl[QKV_SZ];

// ---------------------------------------------------------------------------
// Split fp32 -> bf16 hi + bf16 lo
// ---------------------------------------------------------------------------
__global__ void split_kernel(const float* __restrict__ in, size_t dstOff, int n4)
{
    int i = blockIdx.x * blockDim.x + threadIdx.x;
    if (i >= n4) return;
    float4 v = ((const float4*)in)[i];
    float vv[4] = {v.x, v.y, v.z, v.w};
    __nv_bfloat16 h[4], l[4];
#pragma unroll
    for (int c = 0; c < 4; ++c) {
        h[c] = __float2bfloat16_rn(vv[c]);
        l[c] = __float2bfloat16_rn(vv[c] - __bfloat162float(h[c]));
    }
    __nv_bfloat162* ph = (__nv_bfloat162*)(g_hi + dstOff + (size_t)i * 4);
    __nv_bfloat162* pl = (__nv_bfloat162*)(g_lo + dstOff + (size_t)i * 4);
    ph[0] = __halves2bfloat162(h[0], h[1]);
    ph[1] = __halves2bfloat162(h[2], h[3]);
    pl[0] = __halves2bfloat162(l[0], l[1]);
    pl[1] = __halves2bfloat162(l[2], l[3]);
}

// ---------------------------------------------------------------------------
// MMA helpers
// ---------------------------------------------------------------------------
__device__ __forceinline__ void cp16(uint32_t dst, const void* src)
{
    asm volatile("cp.async.cg.shared.global [%0],[%1],16;\n" :: "r"(dst), "l"(src));
}
__device__ __forceinline__ void ldsm4(uint32_t* r, uint32_t addr)
{
    asm volatile("ldmatrix.sync.aligned.m8n8.x4.shared.b16 {%0,%1,%2,%3},[%4];"
                 : "=r"(r[0]), "=r"(r[1]), "=r"(r[2]), "=r"(r[3]) : "r"(addr));
}
__device__ __forceinline__ void ldsm4t(uint32_t* r, uint32_t addr)
{
    asm volatile("ldmatrix.sync.aligned.m8n8.x4.trans.shared.b16 {%0,%1,%2,%3},[%4];"
                 : "=r"(r[0]), "=r"(r[1]), "=r"(r[2]), "=r"(r[3]) : "r"(addr));
}
__device__ __forceinline__ void mma16816(float* c, const uint32_t* a, const uint32_t* b)
{
    asm volatile(
        "mma.sync.aligned.m16n8k16.row.col.f32.bf16.bf16.f32 "
        "{%0,%1,%2,%3},{%4,%5,%6,%7},{%8,%9},{%0,%1,%2,%3};"
        : "+f"(c[0]), "+f"(c[1]), "+f"(c[2]), "+f"(c[3])
        : "r"(a[0]), "r"(a[1]), "r"(a[2]), "r"(a[3]), "r"(b[0]), "r"(b[1]));
}

// Fast exp: degree-5 poly for 2^f + exponent splice. x <= 0 expected.
__device__ __forceinline__ float fexp(float x)
{
    float t = fmaxf(x * 1.4426950408889634f, -126.0f);
    int n = __float2int_rn(t);
    float f = t - (float)n;
    float p = 1.33336621e-3f;
    p = fmaf(p, f, 9.61812910e-3f);
    p = fmaf(p, f, 5.55041087e-2f);
    p = fmaf(p, f, 2.40226507e-1f);
    p = fmaf(p, f, 6.93147182e-1f);
    p = fmaf(p, f, 1.0f);
    return __int_as_float(__float_as_int(p) + (n << 23));
}

// ---------------------------------------------------------------------------
// Tensor-core GEMM: C = A @ W^T + bias, error-compensated bf16 (3 MMAs).
// QKV==1: fused Q/K/V projection — grid (24, 64), wsel = blockIdx.x>>3.
// QKV==0: output projection (A = attn arena, fp32 row-major C out).
// ---------------------------------------------------------------------------
constexpr int STAGE_B = 40960;

__device__ __forceinline__ void stage_load(
    const __nv_bfloat16* Ah, const __nv_bfloat16* Al,
    const __nv_bfloat16* Wh, const __nv_bfloat16* Wl,
    uint32_t sb, int bm, int bn, int k0, int tid)
{
#pragma unroll
    for (int half = 0; half < 2; ++half) {
        int c = tid + half * 256;
        int row = c >> 2;
        int cc = c & 3;
        uint32_t so = (uint32_t)(row * 80 + cc * 16);
        size_t ga = (size_t)(bm + row) * K_ + k0 + cc * 8;
        size_t gw = (size_t)(bn + row) * K_ + k0 + cc * 8;
        cp16(sb + so,         Ah + ga);
        cp16(sb + 10240 + so, Al + ga);
        cp16(sb + 20480 + so, Wh + gw);
        cp16(sb + 30720 + so, Wl + gw);
    }
    asm volatile("cp.async.commit_group;\n" ::);
}

template<int QKV>
__global__ __launch_bounds__(256, 2)
void mma_gemm(const float* __restrict__ b0p, const float* __restrict__ b1p,
              const float* __restrict__ b2p, float* __restrict__ C)
{
    extern __shared__ __nv_bfloat16 smem_raw[];
    const int tid = threadIdx.x;
    const int lane = tid & 31;
    const int warp = tid >> 5;
    const int wm = warp >> 1;
    const int wn = warp & 1;
    const int bm = blockIdx.y * 128;
    const int wsel = QKV ? (blockIdx.x >> 3) : 0;
    const int bn = (QKV ? (blockIdx.x & 7) : blockIdx.x) * 128;

    const __nv_bfloat16* Ah = g_hi + (QKV ? XOFF : AOFF);
    const __nv_bfloat16* Al = g_lo + (QKV ? XOFF : AOFF);
    const size_t woff = WOFF + (size_t)(QKV ? wsel : 3) * N_ * K_;
    const __nv_bfloat16* Wh = g_hi + woff;
    const __nv_bfloat16* Wl = g_lo + woff;
    const float* bias = QKV ? (wsel == 0 ? b0p : wsel == 1 ? b1p : b2p) : b0p;

    uint32_t sbase = (uint32_t)__cvta_generic_to_shared(smem_raw);

    float acc[2][8][4];
#pragma unroll
    for (int mi = 0; mi < 2; ++mi)
#pragma unroll
        for (int ni = 0; ni < 8; ++ni)
#pragma unroll
            for (int r = 0; r < 4; ++r) acc[mi][ni][r] = 0.0f;

    constexpr int NT = K_ / 32;

    stage_load(Ah, Al, Wh, Wl, sbase, bm, bn, 0, tid);

#pragma unroll 1
    for (int kt = 0; kt < NT; ++kt) {
        const int s = kt & 1;
        if (kt + 1 < NT) {
            stage_load(Ah, Al, Wh, Wl, sbase + (s ^ 1) * STAGE_B, bm, bn, (kt + 1) * 32, tid);
            asm volatile("cp.async.wait_group 1;\n" ::);
        } else {
            asm volatile("cp.async.wait_group 0;\n" ::);
        }
        __syncthreads();

        const uint32_t sb = sbase + s * STAGE_B;
#pragma unroll
        for (int k16 = 0; k16 < 2; ++k16) {
            uint32_t ah[2][4], al[2][4];
#pragma unroll
            for (int mi = 0; mi < 2; ++mi) {
                int row = wm * 32 + mi * 16 + (lane & 15);
                uint32_t off = (uint32_t)(row * 80 + ((lane >> 4) * 8 + k16 * 16) * 2);
                ldsm4(ah[mi], sb + off);
                ldsm4(al[mi], sb + 10240 + off);
            }
#pragma unroll
            for (int nq = 0; nq < 4; ++nq) {
                int wrow = wn * 64 + nq * 16 + (lane & 7) + ((lane >> 4) << 3);
                uint32_t off = (uint32_t)(wrow * 80 + (((lane >> 3) & 1) * 8 + k16 * 16) * 2);
                uint32_t bh[4], bl[4];
                ldsm4(bh, sb + 20480 + off);
                ldsm4(bl, sb + 30720 + off);
#pragma unroll
                for (int mi = 0; mi < 2; ++mi) {
                    mma16816(acc[mi][nq * 2],     ah[mi], bh);
                    mma16816(acc[mi][nq * 2],     ah[mi], bl);
                    mma16816(acc[mi][nq * 2],     al[mi], bh);
                    mma16816(acc[mi][nq * 2 + 1], ah[mi], bh + 2);
                    mma16816(acc[mi][nq * 2 + 1], ah[mi], bl + 2);
                    mma16816(acc[mi][nq * 2 + 1], al[mi], bh + 2);
                }
            }
        }
        __syncthreads();
    }

#pragma unroll
    for (int mi = 0; mi < 2; ++mi) {
#pragma unroll
        for (int ni = 0; ni < 8; ++ni) {
            const int r0 = bm + wm * 32 + mi * 16 + (lane >> 2);
            const int c0 = bn + wn * 64 + ni * 8 + (lane & 3) * 2;
            const float b0 = bias[c0];
            const float b1 = bias[c0 + 1];
            float2 v01 = make_float2(acc[mi][ni][0] + b0, acc[mi][ni][1] + b1);
            float2 v23 = make_float2(acc[mi][ni][2] + b0, acc[mi][ni][3] + b1);
            if (!QKV) {
                *(float2*)&C[(size_t)r0 * N_ + c0] = v01;
                *(float2*)&C[(size_t)(r0 + 8) * N_ + c0] = v23;
            } else {
                __nv_bfloat16* dh = (wsel == 0) ? g_qh : (wsel == 1) ? g_kh : g_vh;
                __nv_bfloat16* dl = (wsel == 0) ? g_ql : (wsel == 1) ? g_kl : g_vl;
                const int h = c0 >> 6;
                const int d = c0 & (DK_ - 1);
#pragma unroll
                for (int rr = 0; rr < 2; ++rr) {
                    const int row = r0 + rr * 8;
                    const int b = row >> 11, t = row & (T_ - 1);
                    const float x0 = rr ? v23.x : v01.x;
                    const float x1 = rr ? v23.y : v01.y;
                    __nv_bfloat16 h0 = __float2bfloat16_rn(x0);
                    __nv_bfloat16 h1 = __float2bfloat16_rn(x1);
                    __nv_bfloat16 l0 = __float2bfloat16_rn(x0 - __bfloat162float(h0));
                    __nv_bfloat16 l1 = __float2bfloat16_rn(x1 - __bfloat162float(h1));
                    size_t off = (((size_t)b * H_ + h) * T_ + t) * DK_ + d;
                    *(__nv_bfloat162*)&dh[off] = __halves2bfloat162(h0, h1);
                    *(__nv_bfloat162*)&dl[off] = __halves2bfloat162(l0, l1);
                }
            }
        }
    }
}

// ---------------------------------------------------------------------------
// Flash attention: 128 query rows per CTA, 8 warps (one 16-row strip each),
// shared KV stages. bf16 MMA with hi/lo compensation, causal.
// smem: Qh/Ql (128x72) + 2 stages of {Kh,Kl,Vh,Vl} (64x72 each) = 110592 B.
// ---------------------------------------------------------------------------
constexpr int AT_STRIDE = 72;
constexpr int AT_KTILE = 64 * AT_STRIDE;                 // one 64-row tile
constexpr int AT_QTILE = 128 * AT_STRIDE;                // 128-row Q tile
constexpr int AT_KVBASE = 2 * AT_QTILE;                  // after Qh, Ql
constexpr int AT_STAGE = 4 * AT_KTILE;                   // Kh,Kl,Vh,Vl
constexpr int AT_SMEM_ELEMS = AT_KVBASE + 2 * AT_STAGE;  // 55296
constexpr int AT_SMEM_BYTES = AT_SMEM_ELEMS * 2;         // 110592

__device__ __forceinline__ void at_load_kv(uint32_t sb, int stage, size_t gbase, int kt, int tid)
{
    const __nv_bfloat16* srcs[4] = {g_kh, g_kl, g_vh, g_vl};
    uint32_t stbase = sb + (AT_KVBASE + stage * AT_STAGE) * 2;
#pragma unroll
    for (int i = 0; i < 8; ++i) {
        const int arr = i >> 1;                  // constant per i
        const int within = (tid + (i & 1) * 256) & 511;
        const int row = within >> 3;
        const int cc = within & 7;
        uint32_t so = stbase + (arr * AT_KTILE + row * AT_STRIDE + cc * 8) * 2;
        cp16(so, srcs[arr] + gbase + (size_t)(kt * 64 + row) * DK_ + cc * 8);
    }
    asm volatile("cp.async.commit_group;\n" ::);
}

__global__ __launch_bounds__(256, 2)
void attn_kernel()
{
    extern __shared__ __nv_bfloat16 at_sm[];
    uint32_t sb = (uint32_t)__cvta_generic_to_shared(at_sm);

    const int tid = threadIdx.x;
    const int lane = tid & 31;
    const int warp = tid >> 5;         // 0..7, 16 query rows each

    const int qt = (int)gridDim.x - 1 - (int)blockIdx.x;   // 128-row tile index
    const int bh = blockIdx.y;
    const size_t gbase = (size_t)bh * T_ * DK_;

    // Load Q tile: 128 rows, hi + lo
    {
        const __nv_bfloat16* srcs[2] = {g_qh, g_ql};
#pragma unroll
        for (int i = 0; i < 8; ++i) {
            const int arr = i >> 2;
            const int within = (tid + (i & 3) * 256) & 1023;
            const int row = within >> 3;
            const int cc = within & 7;
            uint32_t so = sb + (arr * AT_QTILE + row * AT_STRIDE + cc * 8) * 2;
            cp16(so, srcs[arr] + gbase + (size_t)(qt * 128 + row) * DK_ + cc * 8);
        }
    }
    at_load_kv(sb, 0, gbase, 0, tid);

    asm volatile("cp.async.wait_group 0;\n" ::);
    __syncthreads();

    // Hoist Q fragments (4 k16 chunks, hi & lo)
    uint32_t qh[4][4], ql[4][4];
#pragma unroll
    for (int k16 = 0; k16 < 4; ++k16) {
        int row = warp * 16 + (lane & 15);
        uint32_t off = (uint32_t)(row * AT_STRIDE + (lane >> 4) * 8 + k16 * 16) * 2;
        ldsm4(qh[k16], sb + off);
        ldsm4(ql[k16], sb + AT_QTILE * 2 + off);
    }

    float oAcc[8][4];
#pragma unroll
    for (int nt = 0; nt < 8; ++nt)
#pragma unroll
        for (int c = 0; c < 4; ++c) oAcc[nt][c] = 0.0f;

    float m0 = -1e30f, m1 = -1e30f, l0 = 0.0f, l1 = 0.0f;
    const int row0g = qt * 128 + warp * 16 + (lane >> 2);
    const int kt_max = 2 * qt + 1;

#pragma unroll 1
    for (int kt = 0; kt <= kt_max; ++kt) {
        const int s = kt & 1;
        if (kt + 1 <= kt_max) {
            at_load_kv(sb, s ^ 1, gbase, kt + 1, tid);
            asm volatile("cp.async.wait_group 1;\n" ::);
        } else {
            asm volatile("cp.async.wait_group 0;\n" ::);
        }
        __syncthreads();

        const uint32_t kvb = sb + (AT_KVBASE + s * AT_STAGE) * 2;

        // ---- S = Q @ K^T ----
        float sAcc[8][4];
#pragma unroll
        for (int nt = 0; nt < 8; ++nt)
#pragma unroll
            for (int c = 0; c < 4; ++c) sAcc[nt][c] = 0.0f;

#pragma unroll
        for (int k16 = 0; k16 < 4; ++k16) {
#pragma unroll
            for (int np = 0; np < 4; ++np) {
                int krow = np * 16 + (lane & 7) + ((lane >> 4) << 3);
                uint32_t off = (uint32_t)(krow * AT_STRIDE + ((lane >> 3) & 1) * 8 + k16 * 16) * 2;
                uint32_t kh[4], kl[4];
                ldsm4(kh, kvb + off);
                ldsm4(kl, kvb + AT_KTILE * 2 + off);
                mma16816(sAcc[np * 2],     qh[k16], kh);
                mma16816(sAcc[np * 2],     qh[k16], kl);
                mma16816(sAcc[np * 2],     ql[k16], kh);
                mma16816(sAcc[np * 2 + 1], qh[k16], kh + 2);
                mma16816(sAcc[np * 2 + 1], qh[k16], kl + 2);
                mma16816(sAcc[np * 2 + 1], ql[k16], kh + 2);
            }
        }

        // ---- scale + causal mask (only last two key tiles can clip) ----
        const float invs = 0.125f;
        if (kt >= 2 * qt) {
#pragma unroll
            for (int nt = 0; nt < 8; ++nt) {
                const int colb = kt * 64 + nt * 8 + (lane & 3) * 2;
#pragma unroll
                for (int c = 0; c < 4; ++c) {
                    const int col = colb + (c & 1);
                    const int row = row0g + ((c >> 1) << 3);
                    sAcc[nt][c] = (col <= row) ? sAcc[nt][c] * invs : -1e30f;
                }
            }
        } else {
#pragma unroll
            for (int nt = 0; nt < 8; ++nt)
#pragma unroll
                for (int c = 0; c < 4; ++c) sAcc[nt][c] *= invs;
        }

        // ---- online softmax (p kept fp32 in sAcc) ----
        float mx0 = -1e30f, mx1 = -1e30f;
#pragma unroll
        for (int nt = 0; nt < 8; ++nt) {
            mx0 = fmaxf(mx0, fmaxf(sAcc[nt][0], sAcc[nt][1]));
            mx1 = fmaxf(mx1, fmaxf(sAcc[nt][2], sAcc[nt][3]));
        }
        mx0 = fmaxf(mx0, __shfl_xor_sync(0xffffffffu, mx0, 1));
        mx0 = fmaxf(mx0, __shfl_xor_sync(0xffffffffu, mx0, 2));
        mx1 = fmaxf(mx1, __shfl_xor_sync(0xffffffffu, mx1, 1));
        mx1 = fmaxf(mx1, __shfl_xor_sync(0xffffffffu, mx1, 2));

        const float mn0 = fmaxf(m0, mx0);
        const float mn1 = fmaxf(m1, mx1);
        const float fac0 = fexp(m0 - mn0);
        const float fac1 = fexp(m1 - mn1);
        m0 = mn0; m1 = mn1;

        float sum0 = 0.0f, sum1 = 0.0f;
#pragma unroll
        for (int nt = 0; nt < 8; ++nt) {
            sAcc[nt][0] = fexp(sAcc[nt][0] - m0);
            sAcc[nt][1] = fexp(sAcc[nt][1] - m0);
            sAcc[nt][2] = fexp(sAcc[nt][2] - m1);
            sAcc[nt][3] = fexp(sAcc[nt][3] - m1);
            sum0 += sAcc[nt][0] + sAcc[nt][1];
            sum1 += sAcc[nt][2] + sAcc[nt][3];
        }
        sum0 += __shfl_xor_sync(0xffffffffu, sum0, 1);
        sum0 += __shfl_xor_sync(0xffffffffu, sum0, 2);
        sum1 += __shfl_xor_sync(0xffffffffu, sum1, 1);
        sum1 += __shfl_xor_sync(0xffffffffu, sum1, 2);
        l0 = l0 * fac0 + sum0;
        l1 = l1 * fac1 + sum1;

#pragma unroll
        for (int nt = 0; nt < 8; ++nt) {
            oAcc[nt][0] *= fac0; oAcc[nt][1] *= fac0;
            oAcc[nt][2] *= fac1; oAcc[nt][3] *= fac1;
        }

        // ---- O += P @ V (lazy P hi/lo conversion per 16-k chunk) ----
        const uint32_t vb = kvb + 2 * AT_KTILE * 2;   // Vh base
#pragma unroll
        for (int c16 = 0; c16 < 4; ++c16) {
            uint32_t pa_h[4], pa_l[4];
#pragma unroll
            for (int half = 0; half < 2; ++half) {
                const float* pv = sAcc[2 * c16 + half];
                __nv_bfloat16 h0 = __float2bfloat16_rn(pv[0]);
                __nv_bfloat16 h1 = __float2bfloat16_rn(pv[1]);
                __nv_bfloat16 h2 = __float2bfloat16_rn(pv[2]);
                __nv_bfloat16 h3 = __float2bfloat16_rn(pv[3]);
                __nv_bfloat162 hp01 = __halves2bfloat162(h0, h1);
                __nv_bfloat162 hp23 = __halves2bfloat162(h2, h3);
                pa_h[half * 2 + 0] = *(uint32_t*)&hp01;
                pa_h[half * 2 + 1] = *(uint32_t*)&hp23;
                __nv_bfloat162 lp01 = __halves2bfloat162(
                    __float2bfloat16_rn(pv[0] - __bfloat162float(h0)),
                    __float2bfloat16_rn(pv[1] - __bfloat162float(h1)));
                __nv_bfloat162 lp23 = __halves2bfloat162(
                    __float2bfloat16_rn(pv[2] - __bfloat162float(h2)),
                    __float2bfloat16_rn(pv[3] - __bfloat162float(h3)));
                pa_l[half * 2 + 0] = *(uint32_t*)&lp01;
                pa_l[half * 2 + 1] = *(uint32_t*)&lp23;
            }
#pragma unroll
            for (int np = 0; np < 4; ++np) {
                int vrow = c16 * 16 + (lane & 7) + 8 * ((lane >> 3) & 1);
                int vcol = np * 16 + 8 * (lane >> 4);
                uint32_t off = (uint32_t)(vrow * AT_STRIDE + vcol) * 2;
                uint32_t vh[4], vl[4];
                ldsm4t(vh, vb + off);
                ldsm4t(vl, vb + AT_KTILE * 2 + off);
                mma16816(oAcc[np * 2],     pa_h, vh);
                mma16816(oAcc[np * 2],     pa_h, vl);
                mma16816(oAcc[np * 2],     pa_l, vh);
                mma16816(oAcc[np * 2 + 1], pa_h, vh + 2);
                mma16816(oAcc[np * 2 + 1], pa_h, vl + 2);
                mma16816(oAcc[np * 2 + 1], pa_l, vh + 2);
            }
        }
        __syncthreads();
    }

    // ---- epilogue: normalize, write hi/lo bf16 into final-GEMM arena ----
    const float inv0 = 1.0f / l0;
    const float inv1 = 1.0f / l1;
    const int b = bh >> 4;
    const int h = bh & 15;
#pragma unroll
    for (int rr = 0; rr < 2; ++rr) {
        const int t = qt * 128 + warp * 16 + (lane >> 2) + rr * 8;
        const float inv = rr ? inv1 : inv0;
        size_t rowoff = AOFF + ((size_t)b * T_ + t) * D_ + h * DK_ + (lane & 3) * 2;
#pragma unroll
        for (int nt = 0; nt < 8; ++nt) {
            const float x0 = oAcc[nt][rr * 2] * inv;
            const float x1 = oAcc[nt][rr * 2 + 1] * inv;
            __nv_bfloat16 h0 = __float2bfloat16_rn(x0);
            __nv_bfloat16 h1 = __float2bfloat16_rn(x1);
            __nv_bfloat16 lo0 = __float2bfloat16_rn(x0 - __bfloat162float(h0));
            __nv_bfloat16 lo1 = __float2bfloat16_rn(x1 - __bfloat162float(h1));
            *(__nv_bfloat162*)&g_hi[rowoff + nt * 8] = __halves2bfloat162(h0, h1);
            *(__nv_bfloat162*)&g_lo[rowoff + nt * 8] = __halves2bfloat162(lo0, lo1);
        }
    }
}

// ---------------------------------------------------------------------------
// Launch
// ---------------------------------------------------------------------------
extern "C" void kernel_launch(void* const* d_in, const int* in_sizes, int n_in,
                              void* d_out, int out_size)
{
    (void)in_sizes; (void)n_in; (void)out_size;
    const float* x  = (const float*)d_in[0];
    const float* Wq = (const float*)d_in[2];
    const float* Wk = (const float*)d_in[3];
    const float* Wv = (const float*)d_in[4];
    const float* Wo = (const float*)d_in[5];
    const float* bq = (const float*)d_in[6];
    const float* bk = (const float*)d_in[7];
    const float* bv = (const float*)d_in[8];
    const float* bo = (const float*)d_in[9];
    float* out = (float*)d_out;

    const int n4x = M_ * K_ / 4;
    const int n4w = N_ * K_ / 4;
    split_kernel<<<n4x / 256, 256>>>(x,  XOFF, n4x);
    split_kernel<<<n4w / 256, 256>>>(Wq, WOFF + 0ull * N_ * K_, n4w);
    split_kernel<<<n4w / 256, 256>>>(Wk, WOFF + 1ull * N_ * K_, n4w);
    split_kernel<<<n4w / 256, 256>>>(Wv, WOFF + 2ull * N_ * K_, n4w);
    split_kernel<<<n4w / 256, 256>>>(Wo, WOFF + 3ull * N_ * K_, n4w);

    const int gemm_smem = 2 * STAGE_B;
    cudaFuncSetAttribute(mma_gemm<1>, cudaFuncAttributeMaxDynamicSharedMemorySize, gemm_smem);
    cudaFuncSetAttribute(mma_gemm<0>, cudaFuncAttributeMaxDynamicSharedMemorySize, gemm_smem);
    cudaFuncSetAttribute(attn_kernel, cudaFuncAttributeMaxDynamicSharedMemorySize, AT_SMEM_BYTES);

    // Fused QKV projection: grid (3*8, 64)
    mma_gemm<1><<<dim3(24, M_ / 128), 256, gemm_smem>>>(bq, bk, bv, nullptr);

    // Attention: 128 query rows per CTA
    attn_kernel<<<dim3(T_ / 128, B_ * H_), 256, AT_SMEM_BYTES>>>();

    // Output projection
    mma_gemm<0><<<dim3(N_ / 128, M_ / 128), 256, gemm_smem>>>(bo, nullptr, nullptr, out);
}

// round 7
// speedup vs baseline: 1.6058x; 1.6058x over previous
#include <cuda_runtime.h>
#include <cuda_bf16.h>
#include <math.h>
#include <stdint.h>

// Problem constants
constexpr int B_ = 4;
constexpr int T_ = 2048;
constexpr int D_ = 1024;
constexpr int H_ = 16;
constexpr int DK_ = 64;
constexpr int M_ = B_ * T_;   // 8192
constexpr int N_ = D_;        // 1024
constexpr int K_ = D_;        // 1024

// bf16 split arenas (hi + lo). Layout: [x (M*K)][W0..W3 (4*N*K)][attn-out (M*D)]
constexpr size_t XOFF = 0;
constexpr size_t WOFF = (size_t)M_ * K_;
constexpr size_t AOFF = WOFF + 4ull * N_ * K_;
constexpr size_t ARENA = AOFF + (size_t)M_ * D_;

__device__ __nv_bfloat16 g_hi[ARENA];
__device__ __nv_bfloat16 g_lo[ARENA];

// Q/K/V in bf16 hi/lo, layout [B*H, T, DK]
constexpr size_t QKV_SZ = (size_t)B_ * H_ * T_ * DK_;
__device__ __nv_bfloat16 g_qh[QKV_SZ], g_ql[QKV_SZ];
__device__ __nv_bfloat16 g_kh[QKV_SZ], g_kl[QKV_SZ];
__device__ __nv_bfloat16 g_vh[QKV_SZ], g_vl[QKV_SZ];

// ---------------------------------------------------------------------------
// Split fp32 -> bf16 hi + bf16 lo
// ---------------------------------------------------------------------------
__global__ void split_kernel(const float* __restrict__ in, size_t dstOff, int n4)
{
    int i = blockIdx.x * blockDim.x + threadIdx.x;
    if (i >= n4) return;
    float4 v = ((const float4*)in)[i];
    float vv[4] = {v.x, v.y, v.z, v.w};
    __nv_bfloat16 h[4], l[4];
#pragma unroll
    for (int c = 0; c < 4; ++c) {
        h[c] = __float2bfloat16_rn(vv[c]);
        l[c] = __float2bfloat16_rn(vv[c] - __bfloat162float(h[c]));
    }
    __nv_bfloat162* ph = (__nv_bfloat162*)(g_hi + dstOff + (size_t)i * 4);
    __nv_bfloat162* pl = (__nv_bfloat162*)(g_lo + dstOff + (size_t)i * 4);
    ph[0] = __halves2bfloat162(h[0], h[1]);
    ph[1] = __halves2bfloat162(h[2], h[3]);
    pl[0] = __halves2bfloat162(l[0], l[1]);
    pl[1] = __halves2bfloat162(l[2], l[3]);
}

// ---------------------------------------------------------------------------
// MMA helpers
// ---------------------------------------------------------------------------
__device__ __forceinline__ void cp16(uint32_t dst, const void* src)
{
    asm volatile("cp.async.cg.shared.global [%0],[%1],16;\n" :: "r"(dst), "l"(src));
}
__device__ __forceinline__ void ldsm4(uint32_t* r, uint32_t addr)
{
    asm volatile("ldmatrix.sync.aligned.m8n8.x4.shared.b16 {%0,%1,%2,%3},[%4];"
                 : "=r"(r[0]), "=r"(r[1]), "=r"(r[2]), "=r"(r[3]) : "r"(addr));
}
__device__ __forceinline__ void ldsm4t(uint32_t* r, uint32_t addr)
{
    asm volatile("ldmatrix.sync.aligned.m8n8.x4.trans.shared.b16 {%0,%1,%2,%3},[%4];"
                 : "=r"(r[0]), "=r"(r[1]), "=r"(r[2]), "=r"(r[3]) : "r"(addr));
}
__device__ __forceinline__ void mma16816(float* c, const uint32_t* a, const uint32_t* b)
{
    asm volatile(
        "mma.sync.aligned.m16n8k16.row.col.f32.bf16.bf16.f32 "
        "{%0,%1,%2,%3},{%4,%5,%6,%7},{%8,%9},{%0,%1,%2,%3};"
        : "+f"(c[0]), "+f"(c[1]), "+f"(c[2]), "+f"(c[3])
        : "r"(a[0]), "r"(a[1]), "r"(a[2]), "r"(a[3]), "r"(b[0]), "r"(b[1]));
}

// Fast exp: degree-5 poly for 2^f + exponent splice. x <= 0 expected.
__device__ __forceinline__ float fexp(float x)
{
    float t = fmaxf(x * 1.4426950408889634f, -126.0f);
    int n = __float2int_rn(t);
    float f = t - (float)n;
    float p = 1.33336621e-3f;
    p = fmaf(p, f, 9.61812910e-3f);
    p = fmaf(p, f, 5.55041087e-2f);
    p = fmaf(p, f, 2.40226507e-1f);
    p = fmaf(p, f, 6.93147182e-1f);
    p = fmaf(p, f, 1.0f);
    return __int_as_float(__float_as_int(p) + (n << 23));
}

// ---------------------------------------------------------------------------
// Tensor-core GEMM: C = A @ W^T + bias, error-compensated bf16 (3 MMAs).
// QKV==1: fused Q/K/V projection — grid (24, 64), wsel = blockIdx.x>>3.
// QKV==0: output projection (A = attn arena, fp32 row-major C out).
// 128x128 block, BK=32, 8 warps (4m x 2n), 2 CTAs/SM.
// ---------------------------------------------------------------------------
constexpr int STAGE_B = 40960;

__device__ __forceinline__ void stage_load(
    const __nv_bfloat16* Ah, const __nv_bfloat16* Al,
    const __nv_bfloat16* Wh, const __nv_bfloat16* Wl,
    uint32_t sb, int bm, int bn, int k0, int tid)
{
#pragma unroll
    for (int half = 0; half < 2; ++half) {
        int c = tid + half * 256;
        int row = c >> 2;
        int cc = c & 3;
        uint32_t so = (uint32_t)(row * 80 + cc * 16);
        size_t ga = (size_t)(bm + row) * K_ + k0 + cc * 8;
        size_t gw = (size_t)(bn + row) * K_ + k0 + cc * 8;
        cp16(sb + so,         Ah + ga);
        cp16(sb + 10240 + so, Al + ga);
        cp16(sb + 20480 + so, Wh + gw);
        cp16(sb + 30720 + so, Wl + gw);
    }
    asm volatile("cp.async.commit_group;\n" ::);
}

template<int QKV>
__global__ __launch_bounds__(256, 2)
void mma_gemm(const float* __restrict__ b0p, const float* __restrict__ b1p,
              const float* __restrict__ b2p, float* __restrict__ C)
{
    extern __shared__ __nv_bfloat16 smem_raw[];
    const int tid = threadIdx.x;
    const int lane = tid & 31;
    const int warp = tid >> 5;
    const int wm = warp >> 1;
    const int wn = warp & 1;
    const int bm = blockIdx.y * 128;
    const int wsel = QKV ? (blockIdx.x >> 3) : 0;
    const int bn = (QKV ? (blockIdx.x & 7) : blockIdx.x) * 128;

    const __nv_bfloat16* Ah = g_hi + (QKV ? XOFF : AOFF);
    const __nv_bfloat16* Al = g_lo + (QKV ? XOFF : AOFF);
    const size_t woff = WOFF + (size_t)(QKV ? wsel : 3) * N_ * K_;
    const __nv_bfloat16* Wh = g_hi + woff;
    const __nv_bfloat16* Wl = g_lo + woff;
    const float* bias = QKV ? (wsel == 0 ? b0p : wsel == 1 ? b1p : b2p) : b0p;

    uint32_t sbase = (uint32_t)__cvta_generic_to_shared(smem_raw);

    float acc[2][8][4];
#pragma unroll
    for (int mi = 0; mi < 2; ++mi)
#pragma unroll
        for (int ni = 0; ni < 8; ++ni)
#pragma unroll
            for (int r = 0; r < 4; ++r) acc[mi][ni][r] = 0.0f;

    constexpr int NT = K_ / 32;

    stage_load(Ah, Al, Wh, Wl, sbase, bm, bn, 0, tid);

#pragma unroll 1
    for (int kt = 0; kt < NT; ++kt) {
        const int s = kt & 1;
        if (kt + 1 < NT) {
            stage_load(Ah, Al, Wh, Wl, sbase + (s ^ 1) * STAGE_B, bm, bn, (kt + 1) * 32, tid);
            asm volatile("cp.async.wait_group 1;\n" ::);
        } else {
            asm volatile("cp.async.wait_group 0;\n" ::);
        }
        __syncthreads();

        const uint32_t sb = sbase + s * STAGE_B;
#pragma unroll
        for (int k16 = 0; k16 < 2; ++k16) {
            uint32_t ah[2][4], al[2][4];
#pragma unroll
            for (int mi = 0; mi < 2; ++mi) {
                int row = wm * 32 + mi * 16 + (lane & 15);
                uint32_t off = (uint32_t)(row * 80 + ((lane >> 4) * 8 + k16 * 16) * 2);
                ldsm4(ah[mi], sb + off);
                ldsm4(al[mi], sb + 10240 + off);
            }
#pragma unroll
            for (int nq = 0; nq < 4; ++nq) {
                int wrow = wn * 64 + nq * 16 + (lane & 7) + ((lane >> 4) << 3);
                uint32_t off = (uint32_t)(wrow * 80 + (((lane >> 3) & 1) * 8 + k16 * 16) * 2);
                uint32_t bh[4], bl[4];
                ldsm4(bh, sb + 20480 + off);
                ldsm4(bl, sb + 30720 + off);
#pragma unroll
                for (int mi = 0; mi < 2; ++mi) {
                    mma16816(acc[mi][nq * 2],     ah[mi], bh);
                    mma16816(acc[mi][nq * 2],     ah[mi], bl);
                    mma16816(acc[mi][nq * 2],     al[mi], bh);
                    mma16816(acc[mi][nq * 2 + 1], ah[mi], bh + 2);
                    mma16816(acc[mi][nq * 2 + 1], ah[mi], bl + 2);
                    mma16816(acc[mi][nq * 2 + 1], al[mi], bh + 2);
                }
            }
        }
        __syncthreads();
    }

#pragma unroll
    for (int mi = 0; mi < 2; ++mi) {
#pragma unroll
        for (int ni = 0; ni < 8; ++ni) {
            const int r0 = bm + wm * 32 + mi * 16 + (lane >> 2);
            const int c0 = bn + wn * 64 + ni * 8 + (lane & 3) * 2;
            const float b0 = bias[c0];
            const float b1 = bias[c0 + 1];
            float2 v01 = make_float2(acc[mi][ni][0] + b0, acc[mi][ni][1] + b1);
            float2 v23 = make_float2(acc[mi][ni][2] + b0, acc[mi][ni][3] + b1);
            if (!QKV) {
                *(float2*)&C[(size_t)r0 * N_ + c0] = v01;
                *(float2*)&C[(size_t)(r0 + 8) * N_ + c0] = v23;
            } else {
                __nv_bfloat16* dh = (wsel == 0) ? g_qh : (wsel == 1) ? g_kh : g_vh;
                __nv_bfloat16* dl = (wsel == 0) ? g_ql : (wsel == 1) ? g_kl : g_vl;
                const int h = c0 >> 6;
                const int d = c0 & (DK_ - 1);
#pragma unroll
                for (int rr = 0; rr < 2; ++rr) {
                    const int row = r0 + rr * 8;
                    const int b = row >> 11, t = row & (T_ - 1);
                    const float x0 = rr ? v23.x : v01.x;
                    const float x1 = rr ? v23.y : v01.y;
                    __nv_bfloat16 h0 = __float2bfloat16_rn(x0);
                    __nv_bfloat16 h1 = __float2bfloat16_rn(x1);
                    __nv_bfloat16 l0 = __float2bfloat16_rn(x0 - __bfloat162float(h0));
                    __nv_bfloat16 l1 = __float2bfloat16_rn(x1 - __bfloat162float(h1));
                    size_t off = (((size_t)b * H_ + h) * T_ + t) * DK_ + d;
                    *(__nv_bfloat162*)&dh[off] = __halves2bfloat162(h0, h1);
                    *(__nv_bfloat162*)&dl[off] = __halves2bfloat162(l0, l1);
                }
            }
        }
    }
}

// ---------------------------------------------------------------------------
// Flash attention v2: bf16 MMA with hi/lo compensation, causal.
// Block: 128 threads (4 warps), 64 query rows, 64-key tiles, DK=64.
// 2 CTAs/SM (registers: 256 threads/SM -> 256-reg budget, no spills).
// ---------------------------------------------------------------------------
constexpr int AT_STRIDE = 72;
constexpr int AT_TILE = 64 * AT_STRIDE;
constexpr int AT_KVBASE = 2 * AT_TILE;
constexpr int AT_STAGE = 4 * AT_TILE;
constexpr int AT_SMEM_ELEMS = AT_KVBASE + 2 * AT_STAGE;
constexpr int AT_SMEM_BYTES = AT_SMEM_ELEMS * 2;   // 92160

__device__ __forceinline__ void at_load_kv(uint32_t sb, int stage, size_t gbase, int kt, int tid)
{
    const __nv_bfloat16* srcs[4] = {g_kh, g_kl, g_vh, g_vl};
    uint32_t stbase = sb + (AT_KVBASE + stage * AT_STAGE) * 2;
#pragma unroll
    for (int i = 0; i < 16; ++i) {
        const int idx = tid + i * 128;
        const int arr = i >> 2;
        const int within = idx & 511;
        const int row = within >> 3;
        const int cc = within & 7;
        uint32_t so = stbase + (arr * AT_TILE + row * AT_STRIDE + cc * 8) * 2;
        cp16(so, srcs[arr] + gbase + (size_t)(kt * 64 + row) * DK_ + cc * 8);
    }
    asm volatile("cp.async.commit_group;\n" ::);
}

__global__ __launch_bounds__(128, 2)
void attn_kernel()
{
    extern __shared__ __nv_bfloat16 at_sm[];
    uint32_t sb = (uint32_t)__cvta_generic_to_shared(at_sm);

    const int tid = threadIdx.x;
    const int lane = tid & 31;
    const int warp = tid >> 5;

    const int qt = (int)gridDim.x - 1 - (int)blockIdx.x;
    const int bh = blockIdx.y;
    const size_t gbase = (size_t)bh * T_ * DK_;

    {
        const __nv_bfloat16* srcs[2] = {g_qh, g_ql};
#pragma unroll
        for (int i = 0; i < 8; ++i) {
            const int idx = tid + i * 128;
            const int arr = i >> 2;
            const int within = idx & 511;
            const int row = within >> 3;
            const int cc = within & 7;
            uint32_t so = sb + (arr * AT_TILE + row * AT_STRIDE + cc * 8) * 2;
            cp16(so, srcs[arr] + gbase + (size_t)(qt * 64 + row) * DK_ + cc * 8);
        }
    }
    at_load_kv(sb, 0, gbase, 0, tid);

    asm volatile("cp.async.wait_group 0;\n" ::);
    __syncthreads();

    uint32_t qh[4][4], ql[4][4];
#pragma unroll
    for (int k16 = 0; k16 < 4; ++k16) {
        int row = warp * 16 + (lane & 15);
        uint32_t off = (uint32_t)(row * AT_STRIDE + (lane >> 4) * 8 + k16 * 16) * 2;
        ldsm4(qh[k16], sb + off);
        ldsm4(ql[k16], sb + AT_TILE * 2 + off);
    }

    float oAcc[8][4];
#pragma unroll
    for (int nt = 0; nt < 8; ++nt)
#pragma unroll
        for (int c = 0; c < 4; ++c) oAcc[nt][c] = 0.0f;

    float m0 = -1e30f, m1 = -1e30f, l0 = 0.0f, l1 = 0.0f;
    const int row0g = qt * 64 + warp * 16 + (lane >> 2);

#pragma unroll 1
    for (int kt = 0; kt <= qt; ++kt) {
        const int s = kt & 1;
        if (kt + 1 <= qt) {
            at_load_kv(sb, s ^ 1, gbase, kt + 1, tid);
            asm volatile("cp.async.wait_group 1;\n" ::);
        } else {
            asm volatile("cp.async.wait_group 0;\n" ::);
        }
        __syncthreads();

        const uint32_t kvb = sb + (AT_KVBASE + s * AT_STAGE) * 2;

        // ---- S = Q @ K^T ----
        float sAcc[8][4];
#pragma unroll
        for (int nt = 0; nt < 8; ++nt)
#pragma unroll
            for (int c = 0; c < 4; ++c) sAcc[nt][c] = 0.0f;

#pragma unroll
        for (int k16 = 0; k16 < 4; ++k16) {
#pragma unroll
            for (int np = 0; np < 4; ++np) {
                int krow = np * 16 + (lane & 7) + ((lane >> 4) << 3);
                uint32_t off = (uint32_t)(krow * AT_STRIDE + ((lane >> 3) & 1) * 8 + k16 * 16) * 2;
                uint32_t kh[4], kl[4];
                ldsm4(kh, kvb + off);
                ldsm4(kl, kvb + AT_TILE * 2 + off);
                mma16816(sAcc[np * 2],     qh[k16], kh);
                mma16816(sAcc[np * 2],     qh[k16], kl);
                mma16816(sAcc[np * 2],     ql[k16], kh);
                mma16816(sAcc[np * 2 + 1], qh[k16], kh + 2);
                mma16816(sAcc[np * 2 + 1], qh[k16], kl + 2);
                mma16816(sAcc[np * 2 + 1], ql[k16], kh + 2);
            }
        }

        // ---- scale + causal mask ----
        const float invs = 0.125f;
        if (kt == qt) {
#pragma unroll
            for (int nt = 0; nt < 8; ++nt) {
                const int colb = kt * 64 + nt * 8 + (lane & 3) * 2;
#pragma unroll
                for (int c = 0; c < 4; ++c) {
                    const int col = colb + (c & 1);
                    const int row = row0g + ((c >> 1) << 3);
                    sAcc[nt][c] = (col <= row) ? sAcc[nt][c] * invs : -1e30f;
                }
            }
        } else {
#pragma unroll
            for (int nt = 0; nt < 8; ++nt)
#pragma unroll
                for (int c = 0; c < 4; ++c) sAcc[nt][c] *= invs;
        }

        // ---- online softmax (p kept fp32 in sAcc) ----
        float mx0 = -1e30f, mx1 = -1e30f;
#pragma unroll
        for (int nt = 0; nt < 8; ++nt) {
            mx0 = fmaxf(mx0, fmaxf(sAcc[nt][0], sAcc[nt][1]));
            mx1 = fmaxf(mx1, fmaxf(sAcc[nt][2], sAcc[nt][3]));
        }
        mx0 = fmaxf(mx0, __shfl_xor_sync(0xffffffffu, mx0, 1));
        mx0 = fmaxf(mx0, __shfl_xor_sync(0xffffffffu, mx0, 2));
        mx1 = fmaxf(mx1, __shfl_xor_sync(0xffffffffu, mx1, 1));
        mx1 = fmaxf(mx1, __shfl_xor_sync(0xffffffffu, mx1, 2));

        const float mn0 = fmaxf(m0, mx0);
        const float mn1 = fmaxf(m1, mx1);
        const float fac0 = fexp(m0 - mn0);
        const float fac1 = fexp(m1 - mn1);
        m0 = mn0; m1 = mn1;

        float sum0 = 0.0f, sum1 = 0.0f;
#pragma unroll
        for (int nt = 0; nt < 8; ++nt) {
            sAcc[nt][0] = fexp(sAcc[nt][0] - m0);
            sAcc[nt][1] = fexp(sAcc[nt][1] - m0);
            sAcc[nt][2] = fexp(sAcc[nt][2] - m1);
            sAcc[nt][3] = fexp(sAcc[nt][3] - m1);
            sum0 += sAcc[nt][0] + sAcc[nt][1];
            sum1 += sAcc[nt][2] + sAcc[nt][3];
        }
        sum0 += __shfl_xor_sync(0xffffffffu, sum0, 1);
        sum0 += __shfl_xor_sync(0xffffffffu, sum0, 2);
        sum1 += __shfl_xor_sync(0xffffffffu, sum1, 1);
        sum1 += __shfl_xor_sync(0xffffffffu, sum1, 2);
        l0 = l0 * fac0 + sum0;
        l1 = l1 * fac1 + sum1;

#pragma unroll
        for (int nt = 0; nt < 8; ++nt) {
            oAcc[nt][0] *= fac0; oAcc[nt][1] *= fac0;
            oAcc[nt][2] *= fac1; oAcc[nt][3] *= fac1;
        }

        // ---- O += P @ V (lazy P hi/lo conversion per 16-k chunk) ----
        const uint32_t vb = kvb + 2 * AT_TILE * 2;
#pragma unroll
        for (int c16 = 0; c16 < 4; ++c16) {
            uint32_t pa_h[4], pa_l[4];
#pragma unroll
            for (int half = 0; half < 2; ++half) {
                const float* pv = sAcc[2 * c16 + half];
                __nv_bfloat16 h0 = __float2bfloat16_rn(pv[0]);
                __nv_bfloat16 h1 = __float2bfloat16_rn(pv[1]);
                __nv_bfloat16 h2 = __float2bfloat16_rn(pv[2]);
                __nv_bfloat16 h3 = __float2bfloat16_rn(pv[3]);
                __nv_bfloat162 hp01 = __halves2bfloat162(h0, h1);
                __nv_bfloat162 hp23 = __halves2bfloat162(h2, h3);
                pa_h[half * 2 + 0] = *(uint32_t*)&hp01;
                pa_h[half * 2 + 1] = *(uint32_t*)&hp23;
                __nv_bfloat162 lp01 = __halves2bfloat162(
                    __float2bfloat16_rn(pv[0] - __bfloat162float(h0)),
                    __float2bfloat16_rn(pv[1] - __bfloat162float(h1)));
                __nv_bfloat162 lp23 = __halves2bfloat162(
                    __float2bfloat16_rn(pv[2] - __bfloat162float(h2)),
                    __float2bfloat16_rn(pv[3] - __bfloat162float(h3)));
                pa_l[half * 2 + 0] = *(uint32_t*)&lp01;
                pa_l[half * 2 + 1] = *(uint32_t*)&lp23;
            }
#pragma unroll
            for (int np = 0; np < 4; ++np) {
                int vrow = c16 * 16 + (lane & 7) + 8 * ((lane >> 3) & 1);
                int vcol = np * 16 + 8 * (lane >> 4);
                uint32_t off = (uint32_t)(vrow * AT_STRIDE + vcol) * 2;
                uint32_t vh[4], vl[4];
                ldsm4t(vh, vb + off);
                ldsm4t(vl, vb + AT_TILE * 2 + off);
                mma16816(oAcc[np * 2],     pa_h, vh);
                mma16816(oAcc[np * 2],     pa_h, vl);
                mma16816(oAcc[np * 2],     pa_l, vh);
                mma16816(oAcc[np * 2 + 1], pa_h, vh + 2);
                mma16816(oAcc[np * 2 + 1], pa_h, vl + 2);
                mma16816(oAcc[np * 2 + 1], pa_l, vh + 2);
            }
        }
        __syncthreads();
    }

    const float inv0 = 1.0f / l0;
    const float inv1 = 1.0f / l1;
    const int b = bh >> 4;
    const int h = bh & 15;
#pragma unroll
    for (int rr = 0; rr < 2; ++rr) {
        const int t = qt * 64 + warp * 16 + (lane >> 2) + rr * 8;
        const float inv = rr ? inv1 : inv0;
        size_t rowoff = AOFF + ((size_t)b * T_ + t) * D_ + h * DK_ + (lane & 3) * 2;
#pragma unroll
        for (int nt = 0; nt < 8; ++nt) {
            const float x0 = oAcc[nt][rr * 2] * inv;
            const float x1 = oAcc[nt][rr * 2 + 1] * inv;
            __nv_bfloat16 h0 = __float2bfloat16_rn(x0);
            __nv_bfloat16 h1 = __float2bfloat16_rn(x1);
            __nv_bfloat16 lo0 = __float2bfloat16_rn(x0 - __bfloat162float(h0));
            __nv_bfloat16 lo1 = __float2bfloat16_rn(x1 - __bfloat162float(h1));
            *(__nv_bfloat162*)&g_hi[rowoff + nt * 8] = __halves2bfloat162(h0, h1);
            *(__nv_bfloat162*)&g_lo[rowoff + nt * 8] = __halves2bfloat162(lo0, lo1);
        }
    }
}

// ---------------------------------------------------------------------------
// Launch
// ---------------------------------------------------------------------------
extern "C" void kernel_launch(void* const* d_in, const int* in_sizes, int n_in,
                              void* d_out, int out_size)
{
    (void)in_sizes; (void)n_in; (void)out_size;
    const float* x  = (const float*)d_in[0];
    const float* Wq = (const float*)d_in[2];
    const float* Wk = (const float*)d_in[3];
    const float* Wv = (const float*)d_in[4];
    const float* Wo = (const float*)d_in[5];
    const float* bq = (const float*)d_in[6];
    const float* bk = (const float*)d_in[7];
    const float* bv = (const float*)d_in[8];
    const float* bo = (const float*)d_in[9];
    float* out = (float*)d_out;

    const int n4x = M_ * K_ / 4;
    const int n4w = N_ * K_ / 4;
    split_kernel<<<n4x / 256, 256>>>(x,  XOFF, n4x);
    split_kernel<<<n4w / 256, 256>>>(Wq, WOFF + 0ull * N_ * K_, n4w);
    split_kernel<<<n4w / 256, 256>>>(Wk, WOFF + 1ull * N_ * K_, n4w);
    split_kernel<<<n4w / 256, 256>>>(Wv, WOFF + 2ull * N_ * K_, n4w);
    split_kernel<<<n4w / 256, 256>>>(Wo, WOFF + 3ull * N_ * K_, n4w);

    const int gemm_smem = 2 * STAGE_B;
    cudaFuncSetAttribute(mma_gemm<1>, cudaFuncAttributeMaxDynamicSharedMemorySize, gemm_smem);
    cudaFuncSetAttribute(mma_gemm<0>, cudaFuncAttributeMaxDynamicSharedMemorySize, gemm_smem);
    cudaFuncSetAttribute(attn_kernel, cudaFuncAttributeMaxDynamicSharedMemorySize, AT_SMEM_BYTES);

    // Fused QKV projection: grid (3*8, 64)
    mma_gemm<1><<<dim3(24, M_ / 128), 256, gemm_smem>>>(bq, bk, bv, nullptr);

    // Attention: 64 query rows per CTA, 2 CTAs/SM
    attn_kernel<<<dim3(T_ / 64, B_ * H_), 128, AT_SMEM_BYTES>>>();

    // Output projection
    mma_gemm<0><<<dim3(N_ / 128, M_ / 128), 256, gemm_smem>>>(bo, nullptr, nullptr, out);
}

// round 8
// speedup vs baseline: 1.7631x; 1.0980x over previous
#include <cuda_runtime.h>
#include <cuda_bf16.h>
#include <cuda_fp16.h>
#include <math.h>
#include <stdint.h>

// Problem constants
constexpr int B_ = 4;
constexpr int T_ = 2048;
constexpr int D_ = 1024;
constexpr int H_ = 16;
constexpr int DK_ = 64;
constexpr int M_ = B_ * T_;   // 8192
constexpr int N_ = D_;        // 1024
constexpr int K_ = D_;        // 1024

// bf16 split arenas (hi + lo). Layout: [x (M*K)][W0..W3 (4*N*K)][attn-out (M*D)]
constexpr size_t XOFF = 0;
constexpr size_t WOFF = (size_t)M_ * K_;
constexpr size_t AOFF = WOFF + 4ull * N_ * K_;
constexpr size_t ARENA = AOFF + (size_t)M_ * D_;

__device__ __nv_bfloat16 g_hi[ARENA];
__device__ __nv_bfloat16 g_lo[ARENA];

// Q/K in bf16 hi/lo, V in single fp16, layout [B*H, T, DK]
constexpr size_t QKV_SZ = (size_t)B_ * H_ * T_ * DK_;
__device__ __nv_bfloat16 g_qh[QKV_SZ], g_ql[QKV_SZ];
__device__ __nv_bfloat16 g_kh[QKV_SZ], g_kl[QKV_SZ];
__device__ __half g_vf[QKV_SZ];

// ---------------------------------------------------------------------------
// Split fp32 -> bf16 hi + bf16 lo (8 floats per thread, 16B stores)
// ---------------------------------------------------------------------------
__global__ void split_kernel(const float* __restrict__ in, size_t dstOff, int n8)
{
    int i = blockIdx.x * blockDim.x + threadIdx.x;
    if (i >= n8) return;
    const float4* p4 = (const float4*)in;
    float4 a = p4[2 * i], b = p4[2 * i + 1];
    float vv[8] = {a.x, a.y, a.z, a.w, b.x, b.y, b.z, b.w};
    uint32_t hw[4], lw[4];
#pragma unroll
    for (int c = 0; c < 4; ++c) {
        __nv_bfloat16 h0 = __float2bfloat16_rn(vv[2 * c]);
        __nv_bfloat16 h1 = __float2bfloat16_rn(vv[2 * c + 1]);
        __nv_bfloat162 hp = __halves2bfloat162(h0, h1);
        __nv_bfloat162 lp = __halves2bfloat162(
            __float2bfloat16_rn(vv[2 * c] - __bfloat162float(h0)),
            __float2bfloat16_rn(vv[2 * c + 1] - __bfloat162float(h1)));
        hw[c] = *(uint32_t*)&hp;
        lw[c] = *(uint32_t*)&lp;
    }
    *(uint4*)(g_hi + dstOff + (size_t)i * 8) = *(uint4*)hw;
    *(uint4*)(g_lo + dstOff + (size_t)i * 8) = *(uint4*)lw;
}

// ---------------------------------------------------------------------------
// MMA helpers
// ---------------------------------------------------------------------------
__device__ __forceinline__ void cp16(uint32_t dst, const void* src)
{
    asm volatile("cp.async.cg.shared.global [%0],[%1],16;\n" :: "r"(dst), "l"(src));
}
__device__ __forceinline__ void ldsm4(uint32_t* r, uint32_t addr)
{
    asm volatile("ldmatrix.sync.aligned.m8n8.x4.shared.b16 {%0,%1,%2,%3},[%4];"
                 : "=r"(r[0]), "=r"(r[1]), "=r"(r[2]), "=r"(r[3]) : "r"(addr));
}
__device__ __forceinline__ void ldsm4t(uint32_t* r, uint32_t addr)
{
    asm volatile("ldmatrix.sync.aligned.m8n8.x4.trans.shared.b16 {%0,%1,%2,%3},[%4];"
                 : "=r"(r[0]), "=r"(r[1]), "=r"(r[2]), "=r"(r[3]) : "r"(addr));
}
__device__ __forceinline__ void mma16816(float* c, const uint32_t* a, const uint32_t* b)
{
    asm volatile(
        "mma.sync.aligned.m16n8k16.row.col.f32.bf16.bf16.f32 "
        "{%0,%1,%2,%3},{%4,%5,%6,%7},{%8,%9},{%0,%1,%2,%3};"
        : "+f"(c[0]), "+f"(c[1]), "+f"(c[2]), "+f"(c[3])
        : "r"(a[0]), "r"(a[1]), "r"(a[2]), "r"(a[3]), "r"(b[0]), "r"(b[1]));
}
__device__ __forceinline__ void mma16816f(float* c, const uint32_t* a, const uint32_t* b)
{
    asm volatile(
        "mma.sync.aligned.m16n8k16.row.col.f32.f16.f16.f32 "
        "{%0,%1,%2,%3},{%4,%5,%6,%7},{%8,%9},{%0,%1,%2,%3};"
        : "+f"(c[0]), "+f"(c[1]), "+f"(c[2]), "+f"(c[3])
        : "r"(a[0]), "r"(a[1]), "r"(a[2]), "r"(a[3]), "r"(b[0]), "r"(b[1]));
}

// Fast exp: degree-5 poly for 2^f + exponent splice. x <= 0 expected.
__device__ __forceinline__ float fexp(float x)
{
    float t = fmaxf(x * 1.4426950408889634f, -126.0f);
    int n = __float2int_rn(t);
    float f = t - (float)n;
    float p = 1.33336621e-3f;
    p = fmaf(p, f, 9.61812910e-3f);
    p = fmaf(p, f, 5.55041087e-2f);
    p = fmaf(p, f, 2.40226507e-1f);
    p = fmaf(p, f, 6.93147182e-1f);
    p = fmaf(p, f, 1.0f);
    return __int_as_float(__float_as_int(p) + (n << 23));
}

// ---------------------------------------------------------------------------
// Tensor-core GEMM: C = A @ W^T + bias, error-compensated bf16 (3 MMAs).
// QKV==1: fused Q/K/V projection — grid (24, 64), wsel = blockIdx.x>>3.
//         Q/K written bf16 hi/lo; V written single fp16.
// QKV==0: output projection (A = attn arena, fp32 row-major C out).
// ---------------------------------------------------------------------------
constexpr int STAGE_B = 40960;

__device__ __forceinline__ void stage_load(
    const __nv_bfloat16* Ah, const __nv_bfloat16* Al,
    const __nv_bfloat16* Wh, const __nv_bfloat16* Wl,
    uint32_t sb, int bm, int bn, int k0, int tid)
{
#pragma unroll
    for (int half = 0; half < 2; ++half) {
        int c = tid + half * 256;
        int row = c >> 2;
        int cc = c & 3;
        uint32_t so = (uint32_t)(row * 80 + cc * 16);
        size_t ga = (size_t)(bm + row) * K_ + k0 + cc * 8;
        size_t gw = (size_t)(bn + row) * K_ + k0 + cc * 8;
        cp16(sb + so,         Ah + ga);
        cp16(sb + 10240 + so, Al + ga);
        cp16(sb + 20480 + so, Wh + gw);
        cp16(sb + 30720 + so, Wl + gw);
    }
    asm volatile("cp.async.commit_group;\n" ::);
}

template<int QKV>
__global__ __launch_bounds__(256, 2)
void mma_gemm(const float* __restrict__ b0p, const float* __restrict__ b1p,
              const float* __restrict__ b2p, float* __restrict__ C)
{
    extern __shared__ __nv_bfloat16 smem_raw[];
    const int tid = threadIdx.x;
    const int lane = tid & 31;
    const int warp = tid >> 5;
    const int wm = warp >> 1;
    const int wn = warp & 1;
    const int bm = blockIdx.y * 128;
    const int wsel = QKV ? (blockIdx.x >> 3) : 0;
    const int bn = (QKV ? (blockIdx.x & 7) : blockIdx.x) * 128;

    const __nv_bfloat16* Ah = g_hi + (QKV ? XOFF : AOFF);
    const __nv_bfloat16* Al = g_lo + (QKV ? XOFF : AOFF);
    const size_t woff = WOFF + (size_t)(QKV ? wsel : 3) * N_ * K_;
    const __nv_bfloat16* Wh = g_hi + woff;
    const __nv_bfloat16* Wl = g_lo + woff;
    const float* bias = QKV ? (wsel == 0 ? b0p : wsel == 1 ? b1p : b2p) : b0p;

    uint32_t sbase = (uint32_t)__cvta_generic_to_shared(smem_raw);

    float acc[2][8][4];
#pragma unroll
    for (int mi = 0; mi < 2; ++mi)
#pragma unroll
        for (int ni = 0; ni < 8; ++ni)
#pragma unroll
            for (int r = 0; r < 4; ++r) acc[mi][ni][r] = 0.0f;

    constexpr int NT = K_ / 32;

    stage_load(Ah, Al, Wh, Wl, sbase, bm, bn, 0, tid);

#pragma unroll 1
    for (int kt = 0; kt < NT; ++kt) {
        const int s = kt & 1;
        if (kt + 1 < NT) {
            stage_load(Ah, Al, Wh, Wl, sbase + (s ^ 1) * STAGE_B, bm, bn, (kt + 1) * 32, tid);
            asm volatile("cp.async.wait_group 1;\n" ::);
        } else {
            asm volatile("cp.async.wait_group 0;\n" ::);
        }
        __syncthreads();

        const uint32_t sb = sbase + s * STAGE_B;
#pragma unroll
        for (int k16 = 0; k16 < 2; ++k16) {
            uint32_t ah[2][4], al[2][4];
#pragma unroll
            for (int mi = 0; mi < 2; ++mi) {
                int row = wm * 32 + mi * 16 + (lane & 15);
                uint32_t off = (uint32_t)(row * 80 + ((lane >> 4) * 8 + k16 * 16) * 2);
                ldsm4(ah[mi], sb + off);
                ldsm4(al[mi], sb + 10240 + off);
            }
#pragma unroll
            for (int nq = 0; nq < 4; ++nq) {
                int wrow = wn * 64 + nq * 16 + (lane & 7) + ((lane >> 4) << 3);
                uint32_t off = (uint32_t)(wrow * 80 + (((lane >> 3) & 1) * 8 + k16 * 16) * 2);
                uint32_t bh[4], bl[4];
                ldsm4(bh, sb + 20480 + off);
                ldsm4(bl, sb + 30720 + off);
#pragma unroll
                for (int mi = 0; mi < 2; ++mi) {
                    mma16816(acc[mi][nq * 2],     ah[mi], bh);
                    mma16816(acc[mi][nq * 2],     ah[mi], bl);
                    mma16816(acc[mi][nq * 2],     al[mi], bh);
                    mma16816(acc[mi][nq * 2 + 1], ah[mi], bh + 2);
                    mma16816(acc[mi][nq * 2 + 1], ah[mi], bl + 2);
                    mma16816(acc[mi][nq * 2 + 1], al[mi], bh + 2);
                }
            }
        }
        __syncthreads();
    }

#pragma unroll
    for (int mi = 0; mi < 2; ++mi) {
#pragma unroll
        for (int ni = 0; ni < 8; ++ni) {
            const int r0 = bm + wm * 32 + mi * 16 + (lane >> 2);
            const int c0 = bn + wn * 64 + ni * 8 + (lane & 3) * 2;
            const float b0 = bias[c0];
            const float b1 = bias[c0 + 1];
            float2 v01 = make_float2(acc[mi][ni][0] + b0, acc[mi][ni][1] + b1);
            float2 v23 = make_float2(acc[mi][ni][2] + b0, acc[mi][ni][3] + b1);
            if (!QKV) {
                *(float2*)&C[(size_t)r0 * N_ + c0] = v01;
                *(float2*)&C[(size_t)(r0 + 8) * N_ + c0] = v23;
            } else {
                const int h = c0 >> 6;
                const int d = c0 & (DK_ - 1);
#pragma unroll
                for (int rr = 0; rr < 2; ++rr) {
                    const int row = r0 + rr * 8;
                    const int b = row >> 11, t = row & (T_ - 1);
                    const float x0 = rr ? v23.x : v01.x;
                    const float x1 = rr ? v23.y : v01.y;
                    size_t off = (((size_t)b * H_ + h) * T_ + t) * DK_ + d;
                    if (wsel == 2) {
                        *(__half2*)&g_vf[off] = __floats2half2_rn(x0, x1);
                    } else {
                        __nv_bfloat16* dh = (wsel == 0) ? g_qh : g_kh;
                        __nv_bfloat16* dl = (wsel == 0) ? g_ql : g_kl;
                        __nv_bfloat16 h0 = __float2bfloat16_rn(x0);
                        __nv_bfloat16 h1 = __float2bfloat16_rn(x1);
                        __nv_bfloat16 l0 = __float2bfloat16_rn(x0 - __bfloat162float(h0));
                        __nv_bfloat16 l1 = __float2bfloat16_rn(x1 - __bfloat162float(h1));
                        *(__nv_bfloat162*)&dh[off] = __halves2bfloat162(h0, h1);
                        *(__nv_bfloat162*)&dl[off] = __halves2bfloat162(l0, l1);
                    }
                }
            }
        }
    }
}

// ---------------------------------------------------------------------------
// Flash attention v2: S in compensated bf16 (3 MMAs), PV in single fp16 (2).
// Block: 128 threads (4 warps), 64 query rows, 64-key tiles, DK=64. 2 CTAs/SM.
// smem: Qh/Ql (64x72 bf16) + 2 stages of {Kh,Kl(bf16),Vf(fp16)} (64x72 each).
// ---------------------------------------------------------------------------
constexpr int AT_STRIDE = 72;
constexpr int AT_TILE = 64 * AT_STRIDE;
constexpr int AT_KVBASE = 2 * AT_TILE;
constexpr int AT_STAGE = 3 * AT_TILE;                       // Kh,Kl,Vf
constexpr int AT_SMEM_ELEMS = AT_KVBASE + 2 * AT_STAGE;     // 36864
constexpr int AT_SMEM_BYTES = AT_SMEM_ELEMS * 2;            // 73728

__device__ __forceinline__ void at_load_kv(uint32_t sb, int stage, size_t gbase, int kt, int tid)
{
    uint32_t stbase = sb + (AT_KVBASE + stage * AT_STAGE) * 2;
    const void* srcs[3] = {(const void*)g_kh, (const void*)g_kl, (const void*)g_vf};
#pragma unroll
    for (int i = 0; i < 12; ++i) {
        const int arr = i >> 2;
        const int within = (tid + (i & 3) * 128) & 511;
        const int row = within >> 3;
        const int cc = within & 7;
        uint32_t so = stbase + (arr * AT_TILE + row * AT_STRIDE + cc * 8) * 2;
        cp16(so, (const __nv_bfloat16*)srcs[arr] + gbase + (size_t)(kt * 64 + row) * DK_ + cc * 8);
    }
    asm volatile("cp.async.commit_group;\n" ::);
}

__global__ __launch_bounds__(128, 2)
void attn_kernel()
{
    extern __shared__ __nv_bfloat16 at_sm[];
    uint32_t sb = (uint32_t)__cvta_generic_to_shared(at_sm);

    const int tid = threadIdx.x;
    const int lane = tid & 31;
    const int warp = tid >> 5;

    const int qt = (int)gridDim.x - 1 - (int)blockIdx.x;
    const int bh = blockIdx.y;
    const size_t gbase = (size_t)bh * T_ * DK_;

    {
        const __nv_bfloat16* srcs[2] = {g_qh, g_ql};
#pragma unroll
        for (int i = 0; i < 8; ++i) {
            const int idx = tid + i * 128;
            const int arr = i >> 2;
            const int within = idx & 511;
            const int row = within >> 3;
            const int cc = within & 7;
            uint32_t so = sb + (arr * AT_TILE + row * AT_STRIDE + cc * 8) * 2;
            cp16(so, srcs[arr] + gbase + (size_t)(qt * 64 + row) * DK_ + cc * 8);
        }
    }
    at_load_kv(sb, 0, gbase, 0, tid);

    asm volatile("cp.async.wait_group 0;\n" ::);
    __syncthreads();

    uint32_t qh[4][4], ql[4][4];
#pragma unroll
    for (int k16 = 0; k16 < 4; ++k16) {
        int row = warp * 16 + (lane & 15);
        uint32_t off = (uint32_t)(row * AT_STRIDE + (lane >> 4) * 8 + k16 * 16) * 2;
        ldsm4(qh[k16], sb + off);
        ldsm4(ql[k16], sb + AT_TILE * 2 + off);
    }

    float oAcc[8][4];
#pragma unroll
    for (int nt = 0; nt < 8; ++nt)
#pragma unroll
        for (int c = 0; c < 4; ++c) oAcc[nt][c] = 0.0f;

    float m0 = -1e30f, m1 = -1e30f, l0 = 0.0f, l1 = 0.0f;
    const int row0g = qt * 64 + warp * 16 + (lane >> 2);

#pragma unroll 1
    for (int kt = 0; kt <= qt; ++kt) {
        const int s = kt & 1;
        if (kt + 1 <= qt) {
            at_load_kv(sb, s ^ 1, gbase, kt + 1, tid);
            asm volatile("cp.async.wait_group 1;\n" ::);
        } else {
            asm volatile("cp.async.wait_group 0;\n" ::);
        }
        __syncthreads();

        const uint32_t kvb = sb + (AT_KVBASE + s * AT_STAGE) * 2;

        // ---- S = Q @ K^T (bf16 hi/lo compensated) ----
        float sAcc[8][4];
#pragma unroll
        for (int nt = 0; nt < 8; ++nt)
#pragma unroll
            for (int c = 0; c < 4; ++c) sAcc[nt][c] = 0.0f;

#pragma unroll
        for (int k16 = 0; k16 < 4; ++k16) {
#pragma unroll
            for (int np = 0; np < 4; ++np) {
                int krow = np * 16 + (lane & 7) + ((lane >> 4) << 3);
                uint32_t off = (uint32_t)(krow * AT_STRIDE + ((lane >> 3) & 1) * 8 + k16 * 16) * 2;
                uint32_t kh[4], kl[4];
                ldsm4(kh, kvb + off);
                ldsm4(kl, kvb + AT_TILE * 2 + off);
                mma16816(sAcc[np * 2],     qh[k16], kh);
                mma16816(sAcc[np * 2],     qh[k16], kl);
                mma16816(sAcc[np * 2],     ql[k16], kh);
                mma16816(sAcc[np * 2 + 1], qh[k16], kh + 2);
                mma16816(sAcc[np * 2 + 1], qh[k16], kl + 2);
                mma16816(sAcc[np * 2 + 1], ql[k16], kh + 2);
            }
        }

        // ---- scale + causal mask ----
        const float invs = 0.125f;
        if (kt == qt) {
#pragma unroll
            for (int nt = 0; nt < 8; ++nt) {
                const int colb = kt * 64 + nt * 8 + (lane & 3) * 2;
#pragma unroll
                for (int c = 0; c < 4; ++c) {
                    const int col = colb + (c & 1);
                    const int row = row0g + ((c >> 1) << 3);
                    sAcc[nt][c] = (col <= row) ? sAcc[nt][c] * invs : -1e30f;
                }
            }
        } else {
#pragma unroll
            for (int nt = 0; nt < 8; ++nt)
#pragma unroll
                for (int c = 0; c < 4; ++c) sAcc[nt][c] *= invs;
        }

        // ---- online softmax (p kept fp32 in sAcc) ----
        float mx0 = -1e30f, mx1 = -1e30f;
#pragma unroll
        for (int nt = 0; nt < 8; ++nt) {
            mx0 = fmaxf(mx0, fmaxf(sAcc[nt][0], sAcc[nt][1]));
            mx1 = fmaxf(mx1, fmaxf(sAcc[nt][2], sAcc[nt][3]));
        }
        mx0 = fmaxf(mx0, __shfl_xor_sync(0xffffffffu, mx0, 1));
        mx0 = fmaxf(mx0, __shfl_xor_sync(0xffffffffu, mx0, 2));
        mx1 = fmaxf(mx1, __shfl_xor_sync(0xffffffffu, mx1, 1));
        mx1 = fmaxf(mx1, __shfl_xor_sync(0xffffffffu, mx1, 2));

        const float mn0 = fmaxf(m0, mx0);
        const float mn1 = fmaxf(m1, mx1);
        const float fac0 = fexp(m0 - mn0);
        const float fac1 = fexp(m1 - mn1);
        m0 = mn0; m1 = mn1;

        float sum0 = 0.0f, sum1 = 0.0f;
#pragma unroll
        for (int nt = 0; nt < 8; ++nt) {
            sAcc[nt][0] = fexp(sAcc[nt][0] - m0);
            sAcc[nt][1] = fexp(sAcc[nt][1] - m0);
            sAcc[nt][2] = fexp(sAcc[nt][2] - m1);
            sAcc[nt][3] = fexp(sAcc[nt][3] - m1);
            sum0 += sAcc[nt][0] + sAcc[nt][1];
            sum1 += sAcc[nt][2] + sAcc[nt][3];
        }
        sum0 += __shfl_xor_sync(0xffffffffu, sum0, 1);
        sum0 += __shfl_xor_sync(0xffffffffu, sum0, 2);
        sum1 += __shfl_xor_sync(0xffffffffu, sum1, 1);
        sum1 += __shfl_xor_sync(0xffffffffu, sum1, 2);
        l0 = l0 * fac0 + sum0;
        l1 = l1 * fac1 + sum1;

#pragma unroll
        for (int nt = 0; nt < 8; ++nt) {
            oAcc[nt][0] *= fac0; oAcc[nt][1] *= fac0;
            oAcc[nt][2] *= fac1; oAcc[nt][3] *= fac1;
        }

        // ---- O += P @ V (single fp16, 2 MMAs per np) ----
        const uint32_t vb = kvb + 2 * AT_TILE * 2;   // Vf base
#pragma unroll
        for (int c16 = 0; c16 < 4; ++c16) {
            uint32_t pa[4];
#pragma unroll
            for (int half = 0; half < 2; ++half) {
                const float* pv = sAcc[2 * c16 + half];
                __half2 p01 = __floats2half2_rn(pv[0], pv[1]);
                __half2 p23 = __floats2half2_rn(pv[2], pv[3]);
                pa[half * 2 + 0] = *(uint32_t*)&p01;
                pa[half * 2 + 1] = *(uint32_t*)&p23;
            }
#pragma unroll
            for (int np = 0; np < 4; ++np) {
                int vrow = c16 * 16 + (lane & 7) + 8 * ((lane >> 3) & 1);
                int vcol = np * 16 + 8 * (lane >> 4);
                uint32_t off = (uint32_t)(vrow * AT_STRIDE + vcol) * 2;
                uint32_t vf[4];
                ldsm4t(vf, vb + off);
                mma16816f(oAcc[np * 2],     pa, vf);
                mma16816f(oAcc[np * 2 + 1], pa, vf + 2);
            }
        }
        __syncthreads();
    }

    // ---- epilogue: normalize, write hi/lo bf16 into final-GEMM arena ----
    const float inv0 = 1.0f / l0;
    const float inv1 = 1.0f / l1;
    const int b = bh >> 4;
    const int h = bh & 15;
#pragma unroll
    for (int rr = 0; rr < 2; ++rr) {
        const int t = qt * 64 + warp * 16 + (lane >> 2) + rr * 8;
        const float inv = rr ? inv1 : inv0;
        size_t rowoff = AOFF + ((size_t)b * T_ + t) * D_ + h * DK_ + (lane & 3) * 2;
#pragma unroll
        for (int nt = 0; nt < 8; ++nt) {
            const float x0 = oAcc[nt][rr * 2] * inv;
            const float x1 = oAcc[nt][rr * 2 + 1] * inv;
            __nv_bfloat16 h0 = __float2bfloat16_rn(x0);
            __nv_bfloat16 h1 = __float2bfloat16_rn(x1);
            __nv_bfloat16 lo0 = __float2bfloat16_rn(x0 - __bfloat162float(h0));
            __nv_bfloat16 lo1 = __float2bfloat16_rn(x1 - __bfloat162float(h1));
            *(__nv_bfloat162*)&g_hi[rowoff + nt * 8] = __halves2bfloat162(h0, h1);
            *(__nv_bfloat162*)&g_lo[rowoff + nt * 8] = __halves2bfloat162(lo0, lo1);
        }
    }
}

// ---------------------------------------------------------------------------
// Launch
// ---------------------------------------------------------------------------
extern "C" void kernel_launch(void* const* d_in, const int* in_sizes, int n_in,
                              void* d_out, int out_size)
{
    (void)in_sizes; (void)n_in; (void)out_size;
    const float* x  = (const float*)d_in[0];
    const float* Wq = (const float*)d_in[2];
    const float* Wk = (const float*)d_in[3];
    const float* Wv = (const float*)d_in[4];
    const float* Wo = (const float*)d_in[5];
    const float* bq = (const float*)d_in[6];
    const float* bk = (const float*)d_in[7];
    const float* bv = (const float*)d_in[8];
    const float* bo = (const float*)d_in[9];
    float* out = (float*)d_out;

    const int n8x = M_ * K_ / 8;
    const int n8w = N_ * K_ / 8;
    split_kernel<<<n8x / 256, 256>>>(x,  XOFF, n8x);
    split_kernel<<<n8w / 256, 256>>>(Wq, WOFF + 0ull * N_ * K_, n8w);
    split_kernel<<<n8w / 256, 256>>>(Wk, WOFF + 1ull * N_ * K_, n8w);
    split_kernel<<<n8w / 256, 256>>>(Wv, WOFF + 2ull * N_ * K_, n8w);
    split_kernel<<<n8w / 256, 256>>>(Wo, WOFF + 3ull * N_ * K_, n8w);

    const int gemm_smem = 2 * STAGE_B;
    cudaFuncSetAttribute(mma_gemm<1>, cudaFuncAttributeMaxDynamicSharedMemorySize, gemm_smem);
    cudaFuncSetAttribute(mma_gemm<0>, cudaFuncAttributeMaxDynamicSharedMemorySize, gemm_smem);
    cudaFuncSetAttribute(attn_kernel, cudaFuncAttributeMaxDynamicSharedMemorySize, AT_SMEM_BYTES);

    // Fused QKV projection: grid (3*8, 64)
    mma_gemm<1><<<dim3(24, M_ / 128), 256, gemm_smem>>>(bq, bk, bv, nullptr);

    // Attention: 64 query rows per CTA, 2 CTAs/SM
    attn_kernel<<<dim3(T_ / 64, B_ * H_), 128, AT_SMEM_BYTES>>>();

    // Output projection
    mma_gemm<0><<<dim3(N_ / 128, M_ / 128), 256, gemm_smem>>>(bo, nullptr, nullptr, out);
}

// round 9
// speedup vs baseline: 2.3283x; 1.3206x over previous
#include <cuda_runtime.h>
#include <cuda_bf16.h>
#include <cuda_fp16.h>
#include <math.h>
#include <stdint.h>

// Problem constants
constexpr int B_ = 4;
constexpr int T_ = 2048;
constexpr int D_ = 1024;
constexpr int H_ = 16;
constexpr int DK_ = 64;
constexpr int M_ = B_ * T_;   // 8192
constexpr int N_ = D_;        // 1024
constexpr int K_ = D_;        // 1024

// fp16 arenas.
// g_af: A operands, single fp16: [x (M*K)][attn-out (M*D)]
// g_wh/g_wl: weights fp16 hi/lo: [W0..W3 (4*N*K)]
constexpr size_t XOFF = 0;
constexpr size_t AOFF = (size_t)M_ * K_;
constexpr size_t AF_SZ = AOFF + (size_t)M_ * D_;
__device__ __half g_af[AF_SZ];
__device__ __half g_wh[4ull * N_ * K_];
__device__ __half g_wl[4ull * N_ * K_];

// Q/V single fp16, K fp16 hi/lo, layout [B*H, T, DK]
constexpr size_t QKV_SZ = (size_t)B_ * H_ * T_ * DK_;
__device__ __half g_qf[QKV_SZ];
__device__ __half g_kh[QKV_SZ], g_kl[QKV_SZ];
__device__ __half g_vf[QKV_SZ];

// ---------------------------------------------------------------------------
// Converters
// ---------------------------------------------------------------------------
__global__ void conv_f16(const float* __restrict__ in, size_t dstOff, int n8)
{
    int i = blockIdx.x * blockDim.x + threadIdx.x;
    if (i >= n8) return;
    const float4* p4 = (const float4*)in;
    float4 a = p4[2 * i], b = p4[2 * i + 1];
    __half2 h[4];
    h[0] = __floats2half2_rn(a.x, a.y);
    h[1] = __floats2half2_rn(a.z, a.w);
    h[2] = __floats2half2_rn(b.x, b.y);
    h[3] = __floats2half2_rn(b.z, b.w);
    *(uint4*)(g_af + dstOff + (size_t)i * 8) = *(uint4*)h;
}

__global__ void split_w(const float* __restrict__ in, size_t dstOff, int n8)
{
    int i = blockIdx.x * blockDim.x + threadIdx.x;
    if (i >= n8) return;
    const float4* p4 = (const float4*)in;
    float4 a = p4[2 * i], b = p4[2 * i + 1];
    float vv[8] = {a.x, a.y, a.z, a.w, b.x, b.y, b.z, b.w};
    __half hh[8], ll[8];
#pragma unroll
    for (int c = 0; c < 8; ++c) {
        hh[c] = __float2half_rn(vv[c]);
        ll[c] = __float2half_rn(vv[c] - __half2float(hh[c]));
    }
    *(uint4*)(g_wh + dstOff + (size_t)i * 8) = *(uint4*)hh;
    *(uint4*)(g_wl + dstOff + (size_t)i * 8) = *(uint4*)ll;
}

// ---------------------------------------------------------------------------
// MMA helpers
// ---------------------------------------------------------------------------
__device__ __forceinline__ void cp16(uint32_t dst, const void* src)
{
    asm volatile("cp.async.cg.shared.global [%0],[%1],16;\n" :: "r"(dst), "l"(src));
}
__device__ __forceinline__ void ldsm4(uint32_t* r, uint32_t addr)
{
    asm volatile("ldmatrix.sync.aligned.m8n8.x4.shared.b16 {%0,%1,%2,%3},[%4];"
                 : "=r"(r[0]), "=r"(r[1]), "=r"(r[2]), "=r"(r[3]) : "r"(addr));
}
__device__ __forceinline__ void ldsm4t(uint32_t* r, uint32_t addr)
{
    asm volatile("ldmatrix.sync.aligned.m8n8.x4.trans.shared.b16 {%0,%1,%2,%3},[%4];"
                 : "=r"(r[0]), "=r"(r[1]), "=r"(r[2]), "=r"(r[3]) : "r"(addr));
}
__device__ __forceinline__ void mma16816f(float* c, const uint32_t* a, const uint32_t* b)
{
    asm volatile(
        "mma.sync.aligned.m16n8k16.row.col.f32.f16.f16.f32 "
        "{%0,%1,%2,%3},{%4,%5,%6,%7},{%8,%9},{%0,%1,%2,%3};"
        : "+f"(c[0]), "+f"(c[1]), "+f"(c[2]), "+f"(c[3])
        : "r"(a[0]), "r"(a[1]), "r"(a[2]), "r"(a[3]), "r"(b[0]), "r"(b[1]));
}

// Fast exp: degree-5 poly for 2^f + exponent splice. x <= 0 expected.
__device__ __forceinline__ float fexp(float x)
{
    float t = fmaxf(x * 1.4426950408889634f, -126.0f);
    int n = __float2int_rn(t);
    float f = t - (float)n;
    float p = 1.33336621e-3f;
    p = fmaf(p, f, 9.61812910e-3f);
    p = fmaf(p, f, 5.55041087e-2f);
    p = fmaf(p, f, 2.40226507e-1f);
    p = fmaf(p, f, 6.93147182e-1f);
    p = fmaf(p, f, 1.0f);
    return __int_as_float(__float_as_int(p) + (n << 23));
}

// ---------------------------------------------------------------------------
// Tensor-core GEMM: C = A @ W^T + bias. A single fp16, W fp16 hi/lo (2 MMAs).
// QKV==1: fused Q/K/V projection — grid (24, 64), wsel = blockIdx.x>>3.
//         Q,V written single fp16; K written fp16 hi/lo.
// QKV==0: output projection (A = attn arena, fp32 row-major C out).
// smem stage: A (10240 B) | Wh (10240) | Wl (10240) = 30720 B, 2 stages.
// ---------------------------------------------------------------------------
constexpr int STAGE_B = 30720;

__device__ __forceinline__ void stage_load(
    const __half* Af, const __half* Wh, const __half* Wl,
    uint32_t sb, int bm, int bn, int k0, int tid)
{
#pragma unroll
    for (int i = 0; i < 6; ++i) {
        const int arr = i >> 1;                     // 0,0,1,1,2,2
        const int within = tid + (i & 1) * 256;     // 0..511
        const int row = within >> 2;
        const int cc = within & 3;
        uint32_t so = (uint32_t)(arr * 10240 + row * 80 + cc * 16);
        const __half* src = (arr == 0) ? Af + (size_t)(bm + row) * K_ + k0 + cc * 8
                                       : ((arr == 1) ? Wh : Wl) + (size_t)(bn + row) * K_ + k0 + cc * 8;
        cp16(sb + so, src);
    }
    asm volatile("cp.async.commit_group;\n" ::);
}

template<int QKV>
__global__ __launch_bounds__(256, 2)
void mma_gemm(const float* __restrict__ b0p, const float* __restrict__ b1p,
              const float* __restrict__ b2p, float* __restrict__ C)
{
    extern __shared__ __half smem_raw[];
    const int tid = threadIdx.x;
    const int lane = tid & 31;
    const int warp = tid >> 5;
    const int wm = warp >> 1;
    const int wn = warp & 1;
    const int bm = blockIdx.y * 128;
    const int wsel = QKV ? (blockIdx.x >> 3) : 0;
    const int bn = (QKV ? (blockIdx.x & 7) : blockIdx.x) * 128;

    const __half* Af = g_af + (QKV ? XOFF : AOFF);
    const size_t woff = (size_t)(QKV ? wsel : 3) * N_ * K_;
    const __half* Wh = g_wh + woff;
    const __half* Wl = g_wl + woff;
    const float* bias = QKV ? (wsel == 0 ? b0p : wsel == 1 ? b1p : b2p) : b0p;

    uint32_t sbase = (uint32_t)__cvta_generic_to_shared(smem_raw);

    float acc[2][8][4];
#pragma unroll
    for (int mi = 0; mi < 2; ++mi)
#pragma unroll
        for (int ni = 0; ni < 8; ++ni)
#pragma unroll
            for (int r = 0; r < 4; ++r) acc[mi][ni][r] = 0.0f;

    constexpr int NT = K_ / 32;

    stage_load(Af, Wh, Wl, sbase, bm, bn, 0, tid);

#pragma unroll 1
    for (int kt = 0; kt < NT; ++kt) {
        const int s = kt & 1;
        if (kt + 1 < NT) {
            stage_load(Af, Wh, Wl, sbase + (s ^ 1) * STAGE_B, bm, bn, (kt + 1) * 32, tid);
            asm volatile("cp.async.wait_group 1;\n" ::);
        } else {
            asm volatile("cp.async.wait_group 0;\n" ::);
        }
        __syncthreads();

        const uint32_t sb = sbase + s * STAGE_B;
#pragma unroll
        for (int k16 = 0; k16 < 2; ++k16) {
            uint32_t af[2][4];
#pragma unroll
            for (int mi = 0; mi < 2; ++mi) {
                int row = wm * 32 + mi * 16 + (lane & 15);
                uint32_t off = (uint32_t)(row * 80 + ((lane >> 4) * 8 + k16 * 16) * 2);
                ldsm4(af[mi], sb + off);
            }
#pragma unroll
            for (int nq = 0; nq < 4; ++nq) {
                int wrow = wn * 64 + nq * 16 + (lane & 7) + ((lane >> 4) << 3);
                uint32_t off = (uint32_t)(wrow * 80 + (((lane >> 3) & 1) * 8 + k16 * 16) * 2);
                uint32_t wh[4], wl[4];
                ldsm4(wh, sb + 10240 + off);
                ldsm4(wl, sb + 20480 + off);
#pragma unroll
                for (int mi = 0; mi < 2; ++mi) {
                    mma16816f(acc[mi][nq * 2],     af[mi], wh);
                    mma16816f(acc[mi][nq * 2],     af[mi], wl);
                    mma16816f(acc[mi][nq * 2 + 1], af[mi], wh + 2);
                    mma16816f(acc[mi][nq * 2 + 1], af[mi], wl + 2);
                }
            }
        }
        __syncthreads();
    }

#pragma unroll
    for (int mi = 0; mi < 2; ++mi) {
#pragma unroll
        for (int ni = 0; ni < 8; ++ni) {
            const int r0 = bm + wm * 32 + mi * 16 + (lane >> 2);
            const int c0 = bn + wn * 64 + ni * 8 + (lane & 3) * 2;
            const float b0 = bias[c0];
            const float b1 = bias[c0 + 1];
            float2 v01 = make_float2(acc[mi][ni][0] + b0, acc[mi][ni][1] + b1);
            float2 v23 = make_float2(acc[mi][ni][2] + b0, acc[mi][ni][3] + b1);
            if (!QKV) {
                *(float2*)&C[(size_t)r0 * N_ + c0] = v01;
                *(float2*)&C[(size_t)(r0 + 8) * N_ + c0] = v23;
            } else {
                const int h = c0 >> 6;
                const int d = c0 & (DK_ - 1);
#pragma unroll
                for (int rr = 0; rr < 2; ++rr) {
                    const int row = r0 + rr * 8;
                    const int b = row >> 11, t = row & (T_ - 1);
                    const float x0 = rr ? v23.x : v01.x;
                    const float x1 = rr ? v23.y : v01.y;
                    size_t off = (((size_t)b * H_ + h) * T_ + t) * DK_ + d;
                    if (wsel == 1) {
                        __half h0 = __float2half_rn(x0);
                        __half h1 = __float2half_rn(x1);
                        __half l0 = __float2half_rn(x0 - __half2float(h0));
                        __half l1 = __float2half_rn(x1 - __half2float(h1));
                        *(__half2*)&g_kh[off] = __halves2half2(h0, h1);
                        *(__half2*)&g_kl[off] = __halves2half2(l0, l1);
                    } else {
                        __half* dst = (wsel == 0) ? g_qf : g_vf;
                        *(__half2*)&dst[off] = __floats2half2_rn(x0, x1);
                    }
                }
            }
        }
    }
}

// ---------------------------------------------------------------------------
// Flash attention: S = Qf (single fp16) x K (fp16 hi/lo) — 2 MMAs;
// PV single fp16 — 1 matmul. Causal, online softmax.
// Block: 128 threads (4 warps), 64 query rows, 64-key tiles. 2 CTAs/SM.
// smem: Qf (64x72) + 2 stages of {Kh,Kl,Vf} (64x72 each) = 64512 B.
// ---------------------------------------------------------------------------
constexpr int AT_STRIDE = 72;
constexpr int AT_TILE = 64 * AT_STRIDE;
constexpr int AT_KVBASE = AT_TILE;                          // after Qf
constexpr int AT_STAGE = 3 * AT_TILE;                       // Kh,Kl,Vf
constexpr int AT_SMEM_ELEMS = AT_KVBASE + 2 * AT_STAGE;     // 32256
constexpr int AT_SMEM_BYTES = AT_SMEM_ELEMS * 2;            // 64512

__device__ __forceinline__ void at_load_kv(uint32_t sb, int stage, size_t gbase, int kt, int tid)
{
    uint32_t stbase = sb + (AT_KVBASE + stage * AT_STAGE) * 2;
    const __half* srcs[3] = {g_kh, g_kl, g_vf};
#pragma unroll
    for (int i = 0; i < 12; ++i) {
        const int arr = i >> 2;
        const int within = (tid + (i & 3) * 128) & 511;
        const int row = within >> 3;
        const int cc = within & 7;
        uint32_t so = stbase + (arr * AT_TILE + row * AT_STRIDE + cc * 8) * 2;
        cp16(so, srcs[arr] + gbase + (size_t)(kt * 64 + row) * DK_ + cc * 8);
    }
    asm volatile("cp.async.commit_group;\n" ::);
}

__global__ __launch_bounds__(128, 2)
void attn_kernel()
{
    extern __shared__ __half at_sm[];
    uint32_t sb = (uint32_t)__cvta_generic_to_shared(at_sm);

    const int tid = threadIdx.x;
    const int lane = tid & 31;
    const int warp = tid >> 5;

    const int qt = (int)gridDim.x - 1 - (int)blockIdx.x;
    const int bh = blockIdx.y;
    const size_t gbase = (size_t)bh * T_ * DK_;

    // Load Q tile (single fp16)
#pragma unroll
    for (int i = 0; i < 4; ++i) {
        const int within = tid + i * 128;       // 0..511
        const int row = within >> 3;
        const int cc = within & 7;
        uint32_t so = sb + (row * AT_STRIDE + cc * 8) * 2;
        cp16(so, g_qf + gbase + (size_t)(qt * 64 + row) * DK_ + cc * 8);
    }
    at_load_kv(sb, 0, gbase, 0, tid);

    asm volatile("cp.async.wait_group 0;\n" ::);
    __syncthreads();

    uint32_t qf[4][4];
#pragma unroll
    for (int k16 = 0; k16 < 4; ++k16) {
        int row = warp * 16 + (lane & 15);
        uint32_t off = (uint32_t)(row * AT_STRIDE + (lane >> 4) * 8 + k16 * 16) * 2;
        ldsm4(qf[k16], sb + off);
    }

    float oAcc[8][4];
#pragma unroll
    for (int nt = 0; nt < 8; ++nt)
#pragma unroll
        for (int c = 0; c < 4; ++c) oAcc[nt][c] = 0.0f;

    float m0 = -1e30f, m1 = -1e30f, l0 = 0.0f, l1 = 0.0f;
    const int row0g = qt * 64 + warp * 16 + (lane >> 2);

#pragma unroll 1
    for (int kt = 0; kt <= qt; ++kt) {
        const int s = kt & 1;
        if (kt + 1 <= qt) {
            at_load_kv(sb, s ^ 1, gbase, kt + 1, tid);
            asm volatile("cp.async.wait_group 1;\n" ::);
        } else {
            asm volatile("cp.async.wait_group 0;\n" ::);
        }
        __syncthreads();

        const uint32_t kvb = sb + (AT_KVBASE + s * AT_STAGE) * 2;

        // ---- S = Q @ K^T (Q single fp16, K hi/lo) ----
        float sAcc[8][4];
#pragma unroll
        for (int nt = 0; nt < 8; ++nt)
#pragma unroll
            for (int c = 0; c < 4; ++c) sAcc[nt][c] = 0.0f;

#pragma unroll
        for (int k16 = 0; k16 < 4; ++k16) {
#pragma unroll
            for (int np = 0; np < 4; ++np) {
                int krow = np * 16 + (lane & 7) + ((lane >> 4) << 3);
                uint32_t off = (uint32_t)(krow * AT_STRIDE + ((lane >> 3) & 1) * 8 + k16 * 16) * 2;
                uint32_t kh[4], kl[4];
                ldsm4(kh, kvb + off);
                ldsm4(kl, kvb + AT_TILE * 2 + off);
                mma16816f(sAcc[np * 2],     qf[k16], kh);
                mma16816f(sAcc[np * 2],     qf[k16], kl);
                mma16816f(sAcc[np * 2 + 1], qf[k16], kh + 2);
                mma16816f(sAcc[np * 2 + 1], qf[k16], kl + 2);
            }
        }

        // ---- scale + causal mask ----
        const float invs = 0.125f;
        if (kt == qt) {
#pragma unroll
            for (int nt = 0; nt < 8; ++nt) {
                const int colb = kt * 64 + nt * 8 + (lane & 3) * 2;
#pragma unroll
                for (int c = 0; c < 4; ++c) {
                    const int col = colb + (c & 1);
                    const int row = row0g + ((c >> 1) << 3);
                    sAcc[nt][c] = (col <= row) ? sAcc[nt][c] * invs : -1e30f;
                }
            }
        } else {
#pragma unroll
            for (int nt = 0; nt < 8; ++nt)
#pragma unroll
                for (int c = 0; c < 4; ++c) sAcc[nt][c] *= invs;
        }

        // ---- online softmax ----
        float mx0 = -1e30f, mx1 = -1e30f;
#pragma unroll
        for (int nt = 0; nt < 8; ++nt) {
            mx0 = fmaxf(mx0, fmaxf(sAcc[nt][0], sAcc[nt][1]));
            mx1 = fmaxf(mx1, fmaxf(sAcc[nt][2], sAcc[nt][3]));
        }
        mx0 = fmaxf(mx0, __shfl_xor_sync(0xffffffffu, mx0, 1));
        mx0 = fmaxf(mx0, __shfl_xor_sync(0xffffffffu, mx0, 2));
        mx1 = fmaxf(mx1, __shfl_xor_sync(0xffffffffu, mx1, 1));
        mx1 = fmaxf(mx1, __shfl_xor_sync(0xffffffffu, mx1, 2));

        const float mn0 = fmaxf(m0, mx0);
        const float mn1 = fmaxf(m1, mx1);
        const float fac0 = fexp(m0 - mn0);
        const float fac1 = fexp(m1 - mn1);
        m0 = mn0; m1 = mn1;

        float sum0 = 0.0f, sum1 = 0.0f;
#pragma unroll
        for (int nt = 0; nt < 8; ++nt) {
            sAcc[nt][0] = fexp(sAcc[nt][0] - m0);
            sAcc[nt][1] = fexp(sAcc[nt][1] - m0);
            sAcc[nt][2] = fexp(sAcc[nt][2] - m1);
            sAcc[nt][3] = fexp(sAcc[nt][3] - m1);
            sum0 += sAcc[nt][0] + sAcc[nt][1];
            sum1 += sAcc[nt][2] + sAcc[nt][3];
        }
        sum0 += __shfl_xor_sync(0xffffffffu, sum0, 1);
        sum0 += __shfl_xor_sync(0xffffffffu, sum0, 2);
        sum1 += __shfl_xor_sync(0xffffffffu, sum1, 1);
        sum1 += __shfl_xor_sync(0xffffffffu, sum1, 2);
        l0 = l0 * fac0 + sum0;
        l1 = l1 * fac1 + sum1;

#pragma unroll
        for (int nt = 0; nt < 8; ++nt) {
            oAcc[nt][0] *= fac0; oAcc[nt][1] *= fac0;
            oAcc[nt][2] *= fac1; oAcc[nt][3] *= fac1;
        }

        // ---- O += P @ V (single fp16) ----
        const uint32_t vb = kvb + 2 * AT_TILE * 2;   // Vf base
#pragma unroll
        for (int c16 = 0; c16 < 4; ++c16) {
            uint32_t pa[4];
#pragma unroll
            for (int half = 0; half < 2; ++half) {
                const float* pv = sAcc[2 * c16 + half];
                __half2 p01 = __floats2half2_rn(pv[0], pv[1]);
                __half2 p23 = __floats2half2_rn(pv[2], pv[3]);
                pa[half * 2 + 0] = *(uint32_t*)&p01;
                pa[half * 2 + 1] = *(uint32_t*)&p23;
            }
#pragma unroll
            for (int np = 0; np < 4; ++np) {
                int vrow = c16 * 16 + (lane & 7) + 8 * ((lane >> 3) & 1);
                int vcol = np * 16 + 8 * (lane >> 4);
                uint32_t off = (uint32_t)(vrow * AT_STRIDE + vcol) * 2;
                uint32_t vf[4];
                ldsm4t(vf, vb + off);
                mma16816f(oAcc[np * 2],     pa, vf);
                mma16816f(oAcc[np * 2 + 1], pa, vf + 2);
            }
        }
        __syncthreads();
    }

    // ---- epilogue: normalize, write single fp16 into final-GEMM A arena ----
    const float inv0 = 1.0f / l0;
    const float inv1 = 1.0f / l1;
    const int b = bh >> 4;
    const int h = bh & 15;
#pragma unroll
    for (int rr = 0; rr < 2; ++rr) {
        const int t = qt * 64 + warp * 16 + (lane >> 2) + rr * 8;
        const float inv = rr ? inv1 : inv0;
        size_t rowoff = AOFF + ((size_t)b * T_ + t) * D_ + h * DK_ + (lane & 3) * 2;
#pragma unroll
        for (int nt = 0; nt < 8; ++nt) {
            *(__half2*)&g_af[rowoff + nt * 8] = __floats2half2_rn(
                oAcc[nt][rr * 2] * inv, oAcc[nt][rr * 2 + 1] * inv);
        }
    }
}

// ---------------------------------------------------------------------------
// Launch
// ---------------------------------------------------------------------------
extern "C" void kernel_launch(void* const* d_in, const int* in_sizes, int n_in,
                              void* d_out, int out_size)
{
    (void)in_sizes; (void)n_in; (void)out_size;
    const float* x  = (const float*)d_in[0];
    const float* Wq = (const float*)d_in[2];
    const float* Wk = (const float*)d_in[3];
    const float* Wv = (const float*)d_in[4];
    const float* Wo = (const float*)d_in[5];
    const float* bq = (const float*)d_in[6];
    const float* bk = (const float*)d_in[7];
    const float* bv = (const float*)d_in[8];
    const float* bo = (const float*)d_in[9];
    float* out = (float*)d_out;

    const int n8x = M_ * K_ / 8;
    const int n8w = N_ * K_ / 8;
    conv_f16<<<n8x / 256, 256>>>(x, XOFF, n8x);
    split_w<<<n8w / 256, 256>>>(Wq, 0ull * N_ * K_, n8w);
    split_w<<<n8w / 256, 256>>>(Wk, 1ull * N_ * K_, n8w);
    split_w<<<n8w / 256, 256>>>(Wv, 2ull * N_ * K_, n8w);
    split_w<<<n8w / 256, 256>>>(Wo, 3ull * N_ * K_, n8w);

    const int gemm_smem = 2 * STAGE_B;   // 61440
    cudaFuncSetAttribute(mma_gemm<1>, cudaFuncAttributeMaxDynamicSharedMemorySize, gemm_smem);
    cudaFuncSetAttribute(mma_gemm<0>, cudaFuncAttributeMaxDynamicSharedMemorySize, gemm_smem);
    cudaFuncSetAttribute(attn_kernel, cudaFuncAttributeMaxDynamicSharedMemorySize, AT_SMEM_BYTES);

    // Fused QKV projection: grid (3*8, 64)
    mma_gemm<1><<<dim3(24, M_ / 128), 256, gemm_smem>>>(bq, bk, bv, nullptr);

    // Attention: 64 query rows per CTA, 2 CTAs/SM
    attn_kernel<<<dim3(T_ / 64, B_ * H_), 128, AT_SMEM_BYTES>>>();

    // Output projection
    mma_gemm<0><<<dim3(N_ / 128, M_ / 128), 256, gemm_smem>>>(bo, nullptr, nullptr, out);
}

// round 10
// speedup vs baseline: 2.5171x; 1.0811x over previous
#include <cuda_runtime.h>
#include <cuda_fp16.h>
#include <math.h>
#include <stdint.h>

// Problem constants
constexpr int B_ = 4;
constexpr int T_ = 2048;
constexpr int D_ = 1024;
constexpr int H_ = 16;
constexpr int DK_ = 64;
constexpr int M_ = B_ * T_;   // 8192
constexpr int N_ = D_;        // 1024
constexpr int K_ = D_;        // 1024

// fp16 arenas.
// g_af: A operands, single fp16: [x (M*K)][attn-out (M*D)]
// g_wh/g_wl: weights fp16 hi/lo: [W0..W3 (4*N*K)]
constexpr size_t XOFF = 0;
constexpr size_t AOFF = (size_t)M_ * K_;
constexpr size_t AF_SZ = AOFF + (size_t)M_ * D_;
__device__ __half g_af[AF_SZ];
__device__ __half g_wh[4ull * N_ * K_];
__device__ __half g_wl[4ull * N_ * K_];

// Q/K/V single fp16, layout [B*H, T, DK]
constexpr size_t QKV_SZ = (size_t)B_ * H_ * T_ * DK_;
__device__ __half g_qf[QKV_SZ];
__device__ __half g_kf[QKV_SZ];
__device__ __half g_vf[QKV_SZ];

// ---------------------------------------------------------------------------
// Fused converter: x -> g_af (single fp16); W0..W3 -> g_wh/g_wl (hi/lo).
// Grid: [0, NBX) = x blocks; [NBX, NBX+4*NBW) = weight blocks.
// ---------------------------------------------------------------------------
constexpr int NBX = (M_ * K_ / 8) / 256;   // 4096
constexpr int NBW = (N_ * K_ / 8) / 256;   // 512

__global__ void conv_all(const float* __restrict__ x,
                         const float* __restrict__ w0, const float* __restrict__ w1,
                         const float* __restrict__ w2, const float* __restrict__ w3)
{
    const int blk = blockIdx.x;
    if (blk < NBX) {
        int i = blk * 256 + threadIdx.x;
        const float4* p4 = (const float4*)x;
        float4 a = p4[2 * i], b = p4[2 * i + 1];
        __half2 h[4];
        h[0] = __floats2half2_rn(a.x, a.y);
        h[1] = __floats2half2_rn(a.z, a.w);
        h[2] = __floats2half2_rn(b.x, b.y);
        h[3] = __floats2half2_rn(b.z, b.w);
        *(uint4*)(g_af + (size_t)i * 8) = *(uint4*)h;
    } else {
        const int r = blk - NBX;
        const int w = r / NBW;
        const float* src = (w == 0) ? w0 : (w == 1) ? w1 : (w == 2) ? w2 : w3;
        int i = (r % NBW) * 256 + threadIdx.x;
        const float4* p4 = (const float4*)src;
        float4 a = p4[2 * i], b = p4[2 * i + 1];
        float vv[8] = {a.x, a.y, a.z, a.w, b.x, b.y, b.z, b.w};
        __half hh[8], ll[8];
#pragma unroll
        for (int c = 0; c < 8; ++c) {
            hh[c] = __float2half_rn(vv[c]);
            ll[c] = __float2half_rn(vv[c] - __half2float(hh[c]));
        }
        size_t off = (size_t)w * N_ * K_ + (size_t)i * 8;
        *(uint4*)(g_wh + off) = *(uint4*)hh;
        *(uint4*)(g_wl + off) = *(uint4*)ll;
    }
}

// ---------------------------------------------------------------------------
// MMA helpers
// ---------------------------------------------------------------------------
__device__ __forceinline__ void cp16(uint32_t dst, const void* src)
{
    asm volatile("cp.async.cg.shared.global [%0],[%1],16;\n" :: "r"(dst), "l"(src));
}
__device__ __forceinline__ void ldsm4(uint32_t* r, uint32_t addr)
{
    asm volatile("ldmatrix.sync.aligned.m8n8.x4.shared.b16 {%0,%1,%2,%3},[%4];"
                 : "=r"(r[0]), "=r"(r[1]), "=r"(r[2]), "=r"(r[3]) : "r"(addr));
}
__device__ __forceinline__ void ldsm4t(uint32_t* r, uint32_t addr)
{
    asm volatile("ldmatrix.sync.aligned.m8n8.x4.trans.shared.b16 {%0,%1,%2,%3},[%4];"
                 : "=r"(r[0]), "=r"(r[1]), "=r"(r[2]), "=r"(r[3]) : "r"(addr));
}
__device__ __forceinline__ void mma16816f(float* c, const uint32_t* a, const uint32_t* b)
{
    asm volatile(
        "mma.sync.aligned.m16n8k16.row.col.f32.f16.f16.f32 "
        "{%0,%1,%2,%3},{%4,%5,%6,%7},{%8,%9},{%0,%1,%2,%3};"
        : "+f"(c[0]), "+f"(c[1]), "+f"(c[2]), "+f"(c[3])
        : "r"(a[0]), "r"(a[1]), "r"(a[2]), "r"(a[3]), "r"(b[0]), "r"(b[1]));
}

// Fast exp: degree-5 poly for 2^f + exponent splice. x <= 0 expected.
__device__ __forceinline__ float fexp(float x)
{
    float t = fmaxf(x * 1.4426950408889634f, -126.0f);
    int n = __float2int_rn(t);
    float f = t - (float)n;
    float p = 1.33336621e-3f;
    p = fmaf(p, f, 9.61812910e-3f);
    p = fmaf(p, f, 5.55041087e-2f);
    p = fmaf(p, f, 2.40226507e-1f);
    p = fmaf(p, f, 6.93147182e-1f);
    p = fmaf(p, f, 1.0f);
    return __int_as_float(__float_as_int(p) + (n << 23));
}

// ---------------------------------------------------------------------------
// Tensor-core GEMM: C = A @ W^T + bias. A single fp16, W fp16 hi/lo (2 MMAs).
// QKV==1: fused Q/K/V projection — grid (24, 64), wsel = blockIdx.x>>3.
//         Q/K/V written single fp16.
// QKV==0: output projection (A = attn arena, fp32 row-major C out).
// smem stage: A (10240 B) | Wh (10240) | Wl (10240) = 30720 B, 2 stages.
// ---------------------------------------------------------------------------
constexpr int STAGE_B = 30720;

__device__ __forceinline__ void stage_load(
    const __half* Af, const __half* Wh, const __half* Wl,
    uint32_t sb, int bm, int bn, int k0, int tid)
{
#pragma unroll
    for (int i = 0; i < 6; ++i) {
        const int arr = i >> 1;                     // 0,0,1,1,2,2
        const int within = tid + (i & 1) * 256;     // 0..511
        const int row = within >> 2;
        const int cc = within & 3;
        uint32_t so = (uint32_t)(arr * 10240 + row * 80 + cc * 16);
        const __half* src = (arr == 0) ? Af + (size_t)(bm + row) * K_ + k0 + cc * 8
                                       : ((arr == 1) ? Wh : Wl) + (size_t)(bn + row) * K_ + k0 + cc * 8;
        cp16(sb + so, src);
    }
    asm volatile("cp.async.commit_group;\n" ::);
}

template<int QKV>
__global__ __launch_bounds__(256, 2)
void mma_gemm(const float* __restrict__ b0p, const float* __restrict__ b1p,
              const float* __restrict__ b2p, float* __restrict__ C)
{
    extern __shared__ __half smem_raw[];
    const int tid = threadIdx.x;
    const int lane = tid & 31;
    const int warp = tid >> 5;
    const int wm = warp >> 1;
    const int wn = warp & 1;
    const int bm = blockIdx.y * 128;
    const int wsel = QKV ? (blockIdx.x >> 3) : 0;
    const int bn = (QKV ? (blockIdx.x & 7) : blockIdx.x) * 128;

    const __half* Af = g_af + (QKV ? XOFF : AOFF);
    const size_t woff = (size_t)(QKV ? wsel : 3) * N_ * K_;
    const __half* Wh = g_wh + woff;
    const __half* Wl = g_wl + woff;
    const float* bias = QKV ? (wsel == 0 ? b0p : wsel == 1 ? b1p : b2p) : b0p;

    uint32_t sbase = (uint32_t)__cvta_generic_to_shared(smem_raw);

    float acc[2][8][4];
#pragma unroll
    for (int mi = 0; mi < 2; ++mi)
#pragma unroll
        for (int ni = 0; ni < 8; ++ni)
#pragma unroll
            for (int r = 0; r < 4; ++r) acc[mi][ni][r] = 0.0f;

    constexpr int NT = K_ / 32;

    stage_load(Af, Wh, Wl, sbase, bm, bn, 0, tid);

#pragma unroll 1
    for (int kt = 0; kt < NT; ++kt) {
        const int s = kt & 1;
        if (kt + 1 < NT) {
            stage_load(Af, Wh, Wl, sbase + (s ^ 1) * STAGE_B, bm, bn, (kt + 1) * 32, tid);
            asm volatile("cp.async.wait_group 1;\n" ::);
        } else {
            asm volatile("cp.async.wait_group 0;\n" ::);
        }
        __syncthreads();

        const uint32_t sb = sbase + s * STAGE_B;
#pragma unroll
        for (int k16 = 0; k16 < 2; ++k16) {
            uint32_t af[2][4];
#pragma unroll
            for (int mi = 0; mi < 2; ++mi) {
                int row = wm * 32 + mi * 16 + (lane & 15);
                uint32_t off = (uint32_t)(row * 80 + ((lane >> 4) * 8 + k16 * 16) * 2);
                ldsm4(af[mi], sb + off);
            }
#pragma unroll
            for (int nq = 0; nq < 4; ++nq) {
                int wrow = wn * 64 + nq * 16 + (lane & 7) + ((lane >> 4) << 3);
                uint32_t off = (uint32_t)(wrow * 80 + (((lane >> 3) & 1) * 8 + k16 * 16) * 2);
                uint32_t wh[4], wl[4];
                ldsm4(wh, sb + 10240 + off);
                ldsm4(wl, sb + 20480 + off);
#pragma unroll
                for (int mi = 0; mi < 2; ++mi) {
                    mma16816f(acc[mi][nq * 2],     af[mi], wh);
                    mma16816f(acc[mi][nq * 2],     af[mi], wl);
                    mma16816f(acc[mi][nq * 2 + 1], af[mi], wh + 2);
                    mma16816f(acc[mi][nq * 2 + 1], af[mi], wl + 2);
                }
            }
        }
        __syncthreads();
    }

#pragma unroll
    for (int mi = 0; mi < 2; ++mi) {
#pragma unroll
        for (int ni = 0; ni < 8; ++ni) {
            const int r0 = bm + wm * 32 + mi * 16 + (lane >> 2);
            const int c0 = bn + wn * 64 + ni * 8 + (lane & 3) * 2;
            const float b0 = bias[c0];
            const float b1 = bias[c0 + 1];
            float2 v01 = make_float2(acc[mi][ni][0] + b0, acc[mi][ni][1] + b1);
            float2 v23 = make_float2(acc[mi][ni][2] + b0, acc[mi][ni][3] + b1);
            if (!QKV) {
                *(float2*)&C[(size_t)r0 * N_ + c0] = v01;
                *(float2*)&C[(size_t)(r0 + 8) * N_ + c0] = v23;
            } else {
                __half* dst = (wsel == 0) ? g_qf : (wsel == 1) ? g_kf : g_vf;
                const int h = c0 >> 6;
                const int d = c0 & (DK_ - 1);
#pragma unroll
                for (int rr = 0; rr < 2; ++rr) {
                    const int row = r0 + rr * 8;
                    const int b = row >> 11, t = row & (T_ - 1);
                    const float x0 = rr ? v23.x : v01.x;
                    const float x1 = rr ? v23.y : v01.y;
                    size_t off = (((size_t)b * H_ + h) * T_ + t) * DK_ + d;
                    *(__half2*)&dst[off] = __floats2half2_rn(x0, x1);
                }
            }
        }
    }
}

// ---------------------------------------------------------------------------
// Flash attention: S = Qf x Kf (single fp16, 1 MMA per n8); PV single fp16.
// Causal, online softmax. 128 threads (4 warps), 64 query rows. 2 CTAs/SM.
// smem: Qf (64x72) + 2 stages of {Kf,Vf} (64x72 each) = 46080 B.
// ---------------------------------------------------------------------------
constexpr int AT_STRIDE = 72;
constexpr int AT_TILE = 64 * AT_STRIDE;
constexpr int AT_KVBASE = AT_TILE;                          // after Qf
constexpr int AT_STAGE = 2 * AT_TILE;                       // Kf,Vf
constexpr int AT_SMEM_ELEMS = AT_KVBASE + 2 * AT_STAGE;     // 23040
constexpr int AT_SMEM_BYTES = AT_SMEM_ELEMS * 2;            // 46080

__device__ __forceinline__ void at_load_kv(uint32_t sb, int stage, size_t gbase, int kt, int tid)
{
    uint32_t stbase = sb + (AT_KVBASE + stage * AT_STAGE) * 2;
    const __half* srcs[2] = {g_kf, g_vf};
#pragma unroll
    for (int i = 0; i < 8; ++i) {
        const int arr = i >> 2;                       // 0..1, constant per i
        const int within = (tid + (i & 3) * 128) & 511;
        const int row = within >> 3;
        const int cc = within & 7;
        uint32_t so = stbase + (arr * AT_TILE + row * AT_STRIDE + cc * 8) * 2;
        cp16(so, srcs[arr] + gbase + (size_t)(kt * 64 + row) * DK_ + cc * 8);
    }
    asm volatile("cp.async.commit_group;\n" ::);
}

__global__ __launch_bounds__(128, 2)
void attn_kernel()
{
    extern __shared__ __half at_sm[];
    uint32_t sb = (uint32_t)__cvta_generic_to_shared(at_sm);

    const int tid = threadIdx.x;
    const int lane = tid & 31;
    const int warp = tid >> 5;

    const int qt = (int)gridDim.x - 1 - (int)blockIdx.x;
    const int bh = blockIdx.y;
    const size_t gbase = (size_t)bh * T_ * DK_;

    // Load Q tile (single fp16)
#pragma unroll
    for (int i = 0; i < 4; ++i) {
        const int within = tid + i * 128;       // 0..511
        const int row = within >> 3;
        const int cc = within & 7;
        uint32_t so = sb + (row * AT_STRIDE + cc * 8) * 2;
        cp16(so, g_qf + gbase + (size_t)(qt * 64 + row) * DK_ + cc * 8);
    }
    at_load_kv(sb, 0, gbase, 0, tid);

    asm volatile("cp.async.wait_group 0;\n" ::);
    __syncthreads();

    uint32_t qf[4][4];
#pragma unroll
    for (int k16 = 0; k16 < 4; ++k16) {
        int row = warp * 16 + (lane & 15);
        uint32_t off = (uint32_t)(row * AT_STRIDE + (lane >> 4) * 8 + k16 * 16) * 2;
        ldsm4(qf[k16], sb + off);
    }

    float oAcc[8][4];
#pragma unroll
    for (int nt = 0; nt < 8; ++nt)
#pragma unroll
        for (int c = 0; c < 4; ++c) oAcc[nt][c] = 0.0f;

    float m0 = -1e30f, m1 = -1e30f, l0 = 0.0f, l1 = 0.0f;
    const int row0g = qt * 64 + warp * 16 + (lane >> 2);

#pragma unroll 1
    for (int kt = 0; kt <= qt; ++kt) {
        const int s = kt & 1;
        if (kt + 1 <= qt) {
            at_load_kv(sb, s ^ 1, gbase, kt + 1, tid);
            asm volatile("cp.async.wait_group 1;\n" ::);
        } else {
            asm volatile("cp.async.wait_group 0;\n" ::);
        }
        __syncthreads();

        const uint32_t kvb = sb + (AT_KVBASE + s * AT_STAGE) * 2;

        // ---- S = Q @ K^T (single fp16) ----
        float sAcc[8][4];
#pragma unroll
        for (int nt = 0; nt < 8; ++nt)
#pragma unroll
            for (int c = 0; c < 4; ++c) sAcc[nt][c] = 0.0f;

#pragma unroll
        for (int k16 = 0; k16 < 4; ++k16) {
#pragma unroll
            for (int np = 0; np < 4; ++np) {
                int krow = np * 16 + (lane & 7) + ((lane >> 4) << 3);
                uint32_t off = (uint32_t)(krow * AT_STRIDE + ((lane >> 3) & 1) * 8 + k16 * 16) * 2;
                uint32_t kf[4];
                ldsm4(kf, kvb + off);
                mma16816f(sAcc[np * 2],     qf[k16], kf);
                mma16816f(sAcc[np * 2 + 1], qf[k16], kf + 2);
            }
        }

        // ---- scale + causal mask ----
        const float invs = 0.125f;
        if (kt == qt) {
#pragma unroll
            for (int nt = 0; nt < 8; ++nt) {
                const int colb = kt * 64 + nt * 8 + (lane & 3) * 2;
#pragma unroll
                for (int c = 0; c < 4; ++c) {
                    const int col = colb + (c & 1);
                    const int row = row0g + ((c >> 1) << 3);
                    sAcc[nt][c] = (col <= row) ? sAcc[nt][c] * invs : -1e30f;
                }
            }
        } else {
#pragma unroll
            for (int nt = 0; nt < 8; ++nt)
#pragma unroll
                for (int c = 0; c < 4; ++c) sAcc[nt][c] *= invs;
        }

        // ---- online softmax ----
        float mx0 = -1e30f, mx1 = -1e30f;
#pragma unroll
        for (int nt = 0; nt < 8; ++nt) {
            mx0 = fmaxf(mx0, fmaxf(sAcc[nt][0], sAcc[nt][1]));
            mx1 = fmaxf(mx1, fmaxf(sAcc[nt][2], sAcc[nt][3]));
        }
        mx0 = fmaxf(mx0, __shfl_xor_sync(0xffffffffu, mx0, 1));
        mx0 = fmaxf(mx0, __shfl_xor_sync(0xffffffffu, mx0, 2));
        mx1 = fmaxf(mx1, __shfl_xor_sync(0xffffffffu, mx1, 1));
        mx1 = fmaxf(mx1, __shfl_xor_sync(0xffffffffu, mx1, 2));

        const float mn0 = fmaxf(m0, mx0);
        const float mn1 = fmaxf(m1, mx1);
        const float fac0 = fexp(m0 - mn0);
        const float fac1 = fexp(m1 - mn1);
        m0 = mn0; m1 = mn1;

        float sum0 = 0.0f, sum1 = 0.0f;
#pragma unroll
        for (int nt = 0; nt < 8; ++nt) {
            sAcc[nt][0] = fexp(sAcc[nt][0] - m0);
            sAcc[nt][1] = fexp(sAcc[nt][1] - m0);
            sAcc[nt][2] = fexp(sAcc[nt][2] - m1);
            sAcc[nt][3] = fexp(sAcc[nt][3] - m1);
            sum0 += sAcc[nt][0] + sAcc[nt][1];
            sum1 += sAcc[nt][2] + sAcc[nt][3];
        }
        sum0 += __shfl_xor_sync(0xffffffffu, sum0, 1);
        sum0 += __shfl_xor_sync(0xffffffffu, sum0, 2);
        sum1 += __shfl_xor_sync(0xffffffffu, sum1, 1);
        sum1 += __shfl_xor_sync(0xffffffffu, sum1, 2);
        l0 = l0 * fac0 + sum0;
        l1 = l1 * fac1 + sum1;

#pragma unroll
        for (int nt = 0; nt < 8; ++nt) {
            oAcc[nt][0] *= fac0; oAcc[nt][1] *= fac0;
            oAcc[nt][2] *= fac1; oAcc[nt][3] *= fac1;
        }

        // ---- O += P @ V (single fp16) ----
        const uint32_t vb = kvb + AT_TILE * 2;   // Vf base
#pragma unroll
        for (int c16 = 0; c16 < 4; ++c16) {
            uint32_t pa[4];
#pragma unroll
            for (int half = 0; half < 2; ++half) {
                const float* pv = sAcc[2 * c16 + half];
                __half2 p01 = __floats2half2_rn(pv[0], pv[1]);
                __half2 p23 = __floats2half2_rn(pv[2], pv[3]);
                pa[half * 2 + 0] = *(uint32_t*)&p01;
                pa[half * 2 + 1] = *(uint32_t*)&p23;
            }
#pragma unroll
            for (int np = 0; np < 4; ++np) {
                int vrow = c16 * 16 + (lane & 7) + 8 * ((lane >> 3) & 1);
                int vcol = np * 16 + 8 * (lane >> 4);
                uint32_t off = (uint32_t)(vrow * AT_STRIDE + vcol) * 2;
                uint32_t vf[4];
                ldsm4t(vf, vb + off);
                mma16816f(oAcc[np * 2],     pa, vf);
                mma16816f(oAcc[np * 2 + 1], pa, vf + 2);
            }
        }
        __syncthreads();
    }

    // ---- epilogue: normalize, write single fp16 into final-GEMM A arena ----
    const float inv0 = 1.0f / l0;
    const float inv1 = 1.0f / l1;
    const int b = bh >> 4;
    const int h = bh & 15;
#pragma unroll
    for (int rr = 0; rr < 2; ++rr) {
        const int t = qt * 64 + warp * 16 + (lane >> 2) + rr * 8;
        const float inv = rr ? inv1 : inv0;
        size_t rowoff = AOFF + ((size_t)b * T_ + t) * D_ + h * DK_ + (lane & 3) * 2;
#pragma unroll
        for (int nt = 0; nt < 8; ++nt) {
            *(__half2*)&g_af[rowoff + nt * 8] = __floats2half2_rn(
                oAcc[nt][rr * 2] * inv, oAcc[nt][rr * 2 + 1] * inv);
        }
    }
}

// ---------------------------------------------------------------------------
// Launch
// ---------------------------------------------------------------------------
extern "C" void kernel_launch(void* const* d_in, const int* in_sizes, int n_in,
                              void* d_out, int out_size)
{
    (void)in_sizes; (void)n_in; (void)out_size;
    const float* x  = (const float*)d_in[0];
    const float* Wq = (const float*)d_in[2];
    const float* Wk = (const float*)d_in[3];
    const float* Wv = (const float*)d_in[4];
    const float* Wo = (const float*)d_in[5];
    const float* bq = (const float*)d_in[6];
    const float* bk = (const float*)d_in[7];
    const float* bv = (const float*)d_in[8];
    const float* bo = (const float*)d_in[9];
    float* out = (float*)d_out;

    // Fused conversions: x + 4 weights in one launch
    conv_all<<<NBX + 4 * NBW, 256>>>(x, Wq, Wk, Wv, Wo);

    const int gemm_smem = 2 * STAGE_B;   // 61440
    cudaFuncSetAttribute(mma_gemm<1>, cudaFuncAttributeMaxDynamicSharedMemorySize, gemm_smem);
    cudaFuncSetAttribute(mma_gemm<0>, cudaFuncAttributeMaxDynamicSharedMemorySize, gemm_smem);
    cudaFuncSetAttribute(attn_kernel, cudaFuncAttributeMaxDynamicSharedMemorySize, AT_SMEM_BYTES);

    // Fused QKV projection: grid (3*8, 64)
    mma_gemm<1><<<dim3(24, M_ / 128), 256, gemm_smem>>>(bq, bk, bv, nullptr);

    // Attention: 64 query rows per CTA, 2 CTAs/SM
    attn_kernel<<<dim3(T_ / 64, B_ * H_), 128, AT_SMEM_BYTES>>>();

    // Output projection
    mma_gemm<0><<<dim3(N_ / 128, M_ / 128), 256, gemm_smem>>>(bo, nullptr, nullptr, out);
}

// round 11
// speedup vs baseline: 2.5368x; 1.0078x over previous
#include <cuda_runtime.h>
#include <cuda_fp16.h>
#include <math.h>
#include <stdint.h>

// Problem constants
constexpr int B_ = 4;
constexpr int T_ = 2048;
constexpr int D_ = 1024;
constexpr int H_ = 16;
constexpr int DK_ = 64;
constexpr int M_ = B_ * T_;   // 8192
constexpr int N_ = D_;        // 1024
constexpr int K_ = D_;        // 1024

// fp16 arenas.
constexpr size_t XOFF = 0;
constexpr size_t AOFF = (size_t)M_ * K_;
constexpr size_t AF_SZ = AOFF + (size_t)M_ * D_;
__device__ __half g_af[AF_SZ];
__device__ __half g_wh[4ull * N_ * K_];
__device__ __half g_wl[4ull * N_ * K_];

// Q/K/V single fp16, layout [B*H, T, DK]
constexpr size_t QKV_SZ = (size_t)B_ * H_ * T_ * DK_;
__device__ __half g_qf[QKV_SZ];
__device__ __half g_kf[QKV_SZ];
__device__ __half g_vf[QKV_SZ];

// ---------------------------------------------------------------------------
// Fused converter
// ---------------------------------------------------------------------------
constexpr int NBX = (M_ * K_ / 8) / 256;   // 4096
constexpr int NBW = (N_ * K_ / 8) / 256;   // 512

__global__ void conv_all(const float* __restrict__ x,
                         const float* __restrict__ w0, const float* __restrict__ w1,
                         const float* __restrict__ w2, const float* __restrict__ w3)
{
    const int blk = blockIdx.x;
    if (blk < NBX) {
        int i = blk * 256 + threadIdx.x;
        const float4* p4 = (const float4*)x;
        float4 a = p4[2 * i], b = p4[2 * i + 1];
        __half2 h[4];
        h[0] = __floats2half2_rn(a.x, a.y);
        h[1] = __floats2half2_rn(a.z, a.w);
        h[2] = __floats2half2_rn(b.x, b.y);
        h[3] = __floats2half2_rn(b.z, b.w);
        *(uint4*)(g_af + (size_t)i * 8) = *(uint4*)h;
    } else {
        const int r = blk - NBX;
        const int w = r / NBW;
        const float* src = (w == 0) ? w0 : (w == 1) ? w1 : (w == 2) ? w2 : w3;
        int i = (r % NBW) * 256 + threadIdx.x;
        const float4* p4 = (const float4*)src;
        float4 a = p4[2 * i], b = p4[2 * i + 1];
        float vv[8] = {a.x, a.y, a.z, a.w, b.x, b.y, b.z, b.w};
        __half hh[8], ll[8];
#pragma unroll
        for (int c = 0; c < 8; ++c) {
            hh[c] = __float2half_rn(vv[c]);
            ll[c] = __float2half_rn(vv[c] - __half2float(hh[c]));
        }
        size_t off = (size_t)w * N_ * K_ + (size_t)i * 8;
        *(uint4*)(g_wh + off) = *(uint4*)hh;
        *(uint4*)(g_wl + off) = *(uint4*)ll;
    }
}

// ---------------------------------------------------------------------------
// MMA helpers
// ---------------------------------------------------------------------------
__device__ __forceinline__ void cp16(uint32_t dst, const void* src)
{
    asm volatile("cp.async.cg.shared.global [%0],[%1],16;\n" :: "r"(dst), "l"(src));
}
__device__ __forceinline__ void ldsm4(uint32_t* r, uint32_t addr)
{
    asm volatile("ldmatrix.sync.aligned.m8n8.x4.shared.b16 {%0,%1,%2,%3},[%4];"
                 : "=r"(r[0]), "=r"(r[1]), "=r"(r[2]), "=r"(r[3]) : "r"(addr));
}
__device__ __forceinline__ void ldsm4t(uint32_t* r, uint32_t addr)
{
    asm volatile("ldmatrix.sync.aligned.m8n8.x4.trans.shared.b16 {%0,%1,%2,%3},[%4];"
                 : "=r"(r[0]), "=r"(r[1]), "=r"(r[2]), "=r"(r[3]) : "r"(addr));
}
__device__ __forceinline__ void mma16816f(float* c, const uint32_t* a, const uint32_t* b)
{
    asm volatile(
        "mma.sync.aligned.m16n8k16.row.col.f32.f16.f16.f32 "
        "{%0,%1,%2,%3},{%4,%5,%6,%7},{%8,%9},{%0,%1,%2,%3};"
        : "+f"(c[0]), "+f"(c[1]), "+f"(c[2]), "+f"(c[3])
        : "r"(a[0]), "r"(a[1]), "r"(a[2]), "r"(a[3]), "r"(b[0]), "r"(b[1]));
}

// Fast exp: degree-5 poly for 2^f + exponent splice. x <= 0 expected.
__device__ __forceinline__ float fexp(float x)
{
    float t = fmaxf(x * 1.4426950408889634f, -126.0f);
    int n = __float2int_rn(t);
    float f = t - (float)n;
    float p = 1.33336621e-3f;
    p = fmaf(p, f, 9.61812910e-3f);
    p = fmaf(p, f, 5.55041087e-2f);
    p = fmaf(p, f, 2.40226507e-1f);
    p = fmaf(p, f, 6.93147182e-1f);
    p = fmaf(p, f, 1.0f);
    return __int_as_float(__float_as_int(p) + (n << 23));
}

// ---------------------------------------------------------------------------
// Tensor-core GEMM: C = A @ W^T + bias. A single fp16, W fp16 hi/lo (2 MMAs).
// 3-stage cp.async pipeline, one __syncthreads per k-tile, interleaved MMAs.
// ---------------------------------------------------------------------------
constexpr int STAGE_B = 30720;
constexpr int G_NSTG = 3;

__device__ __forceinline__ void stage_load(
    const __half* Af, const __half* Wh, const __half* Wl,
    uint32_t sb, int bm, int bn, int k0, int tid)
{
#pragma unroll
    for (int i = 0; i < 6; ++i) {
        const int arr = i >> 1;
        const int within = tid + (i & 1) * 256;
        const int row = within >> 2;
        const int cc = within & 3;
        uint32_t so = (uint32_t)(arr * 10240 + row * 80 + cc * 16);
        const __half* src = (arr == 0) ? Af + (size_t)(bm + row) * K_ + k0 + cc * 8
                                       : ((arr == 1) ? Wh : Wl) + (size_t)(bn + row) * K_ + k0 + cc * 8;
        cp16(sb + so, src);
    }
    asm volatile("cp.async.commit_group;\n" ::);
}

template<int QKV>
__global__ __launch_bounds__(256, 2)
void mma_gemm(const float* __restrict__ b0p, const float* __restrict__ b1p,
              const float* __restrict__ b2p, float* __restrict__ C)
{
    extern __shared__ __half smem_raw[];
    const int tid = threadIdx.x;
    const int lane = tid & 31;
    const int warp = tid >> 5;
    const int wm = warp >> 1;
    const int wn = warp & 1;
    const int bm = blockIdx.y * 128;
    const int wsel = QKV ? (blockIdx.x >> 3) : 0;
    const int bn = (QKV ? (blockIdx.x & 7) : blockIdx.x) * 128;

    const __half* Af = g_af + (QKV ? XOFF : AOFF);
    const size_t woff = (size_t)(QKV ? wsel : 3) * N_ * K_;
    const __half* Wh = g_wh + woff;
    const __half* Wl = g_wl + woff;
    const float* bias = QKV ? (wsel == 0 ? b0p : wsel == 1 ? b1p : b2p) : b0p;

    uint32_t sbase = (uint32_t)__cvta_generic_to_shared(smem_raw);

    float acc[2][8][4];
#pragma unroll
    for (int mi = 0; mi < 2; ++mi)
#pragma unroll
        for (int ni = 0; ni < 8; ++ni)
#pragma unroll
            for (int r = 0; r < 4; ++r) acc[mi][ni][r] = 0.0f;

    constexpr int NT = K_ / 32;

    stage_load(Af, Wh, Wl, sbase, bm, bn, 0, tid);
    stage_load(Af, Wh, Wl, sbase + STAGE_B, bm, bn, 32, tid);

#pragma unroll 1
    for (int kt = 0; kt < NT; ++kt) {
        const int s = kt % G_NSTG;
        if (kt + 1 < NT) {
            asm volatile("cp.async.wait_group 1;\n" ::);
        } else {
            asm volatile("cp.async.wait_group 0;\n" ::);
        }
        __syncthreads();
        if (kt + 2 < NT)
            stage_load(Af, Wh, Wl, sbase + ((kt + 2) % G_NSTG) * STAGE_B,
                       bm, bn, (kt + 2) * 32, tid);

        const uint32_t sb = sbase + s * STAGE_B;
#pragma unroll
        for (int k16 = 0; k16 < 2; ++k16) {
            uint32_t af[2][4];
#pragma unroll
            for (int mi = 0; mi < 2; ++mi) {
                int row = wm * 32 + mi * 16 + (lane & 15);
                uint32_t off = (uint32_t)(row * 80 + ((lane >> 4) * 8 + k16 * 16) * 2);
                ldsm4(af[mi], sb + off);
            }
#pragma unroll
            for (int nq = 0; nq < 4; ++nq) {
                int wrow = wn * 64 + nq * 16 + (lane & 7) + ((lane >> 4) << 3);
                uint32_t off = (uint32_t)(wrow * 80 + (((lane >> 3) & 1) * 8 + k16 * 16) * 2);
                uint32_t wh[4], wl[4];
                ldsm4(wh, sb + 10240 + off);
                ldsm4(wl, sb + 20480 + off);
                // Interleaved: consecutive MMAs hit distinct accumulators (RAW dist 4)
                mma16816f(acc[0][nq * 2],     af[0], wh);
                mma16816f(acc[0][nq * 2 + 1], af[0], wh + 2);
                mma16816f(acc[1][nq * 2],     af[1], wh);
                mma16816f(acc[1][nq * 2 + 1], af[1], wh + 2);
                mma16816f(acc[0][nq * 2],     af[0], wl);
                mma16816f(acc[0][nq * 2 + 1], af[0], wl + 2);
                mma16816f(acc[1][nq * 2],     af[1], wl);
                mma16816f(acc[1][nq * 2 + 1], af[1], wl + 2);
            }
        }
    }

#pragma unroll
    for (int mi = 0; mi < 2; ++mi) {
#pragma unroll
        for (int ni = 0; ni < 8; ++ni) {
            const int r0 = bm + wm * 32 + mi * 16 + (lane >> 2);
            const int c0 = bn + wn * 64 + ni * 8 + (lane & 3) * 2;
            const float b0 = bias[c0];
            const float b1 = bias[c0 + 1];
            float2 v01 = make_float2(acc[mi][ni][0] + b0, acc[mi][ni][1] + b1);
            float2 v23 = make_float2(acc[mi][ni][2] + b0, acc[mi][ni][3] + b1);
            if (!QKV) {
                *(float2*)&C[(size_t)r0 * N_ + c0] = v01;
                *(float2*)&C[(size_t)(r0 + 8) * N_ + c0] = v23;
            } else {
                __half* dst = (wsel == 0) ? g_qf : (wsel == 1) ? g_kf : g_vf;
                const int h = c0 >> 6;
                const int d = c0 & (DK_ - 1);
#pragma unroll
                for (int rr = 0; rr < 2; ++rr) {
                    const int row = r0 + rr * 8;
                    const int b = row >> 11, t = row & (T_ - 1);
                    const float x0 = rr ? v23.x : v01.x;
                    const float x1 = rr ? v23.y : v01.y;
                    size_t off = (((size_t)b * H_ + h) * T_ + t) * DK_ + d;
                    *(__half2*)&dst[off] = __floats2half2_rn(x0, x1);
                }
            }
        }
    }
}

// ---------------------------------------------------------------------------
// Flash attention: single fp16 QK^T and PV. Causal, online softmax.
// One __syncthreads per KV tile. 128 threads, 64 query rows. 2 CTAs/SM.
// ---------------------------------------------------------------------------
constexpr int AT_STRIDE = 72;
constexpr int AT_TILE = 64 * AT_STRIDE;
constexpr int AT_KVBASE = AT_TILE;                          // after Qf
constexpr int AT_STAGE = 2 * AT_TILE;                       // Kf,Vf
constexpr int AT_SMEM_ELEMS = AT_KVBASE + 2 * AT_STAGE;     // 23040
constexpr int AT_SMEM_BYTES = AT_SMEM_ELEMS * 2;            // 46080

__device__ __forceinline__ void at_load_kv(uint32_t sb, int stage, size_t gbase, int kt, int tid)
{
    uint32_t stbase = sb + (AT_KVBASE + stage * AT_STAGE) * 2;
    const __half* srcs[2] = {g_kf, g_vf};
#pragma unroll
    for (int i = 0; i < 8; ++i) {
        const int arr = i >> 2;
        const int within = (tid + (i & 3) * 128) & 511;
        const int row = within >> 3;
        const int cc = within & 7;
        uint32_t so = stbase + (arr * AT_TILE + row * AT_STRIDE + cc * 8) * 2;
        cp16(so, srcs[arr] + gbase + (size_t)(kt * 64 + row) * DK_ + cc * 8);
    }
    asm volatile("cp.async.commit_group;\n" ::);
}

__global__ __launch_bounds__(128, 2)
void attn_kernel()
{
    extern __shared__ __half at_sm[];
    uint32_t sb = (uint32_t)__cvta_generic_to_shared(at_sm);

    const int tid = threadIdx.x;
    const int lane = tid & 31;
    const int warp = tid >> 5;

    const int qt = (int)gridDim.x - 1 - (int)blockIdx.x;
    const int bh = blockIdx.y;
    const size_t gbase = (size_t)bh * T_ * DK_;

    // Prologue: load Q + KV stage 0 (one group)
#pragma unroll
    for (int i = 0; i < 4; ++i) {
        const int within = tid + i * 128;
        const int row = within >> 3;
        const int cc = within & 7;
        uint32_t so = sb + (row * AT_STRIDE + cc * 8) * 2;
        cp16(so, g_qf + gbase + (size_t)(qt * 64 + row) * DK_ + cc * 8);
    }
    at_load_kv(sb, 0, gbase, 0, tid);

    float oAcc[8][4];
#pragma unroll
    for (int nt = 0; nt < 8; ++nt)
#pragma unroll
        for (int c = 0; c < 4; ++c) oAcc[nt][c] = 0.0f;

    float m0 = -1e30f, m1 = -1e30f, l0 = 0.0f, l1 = 0.0f;
    const int row0g = qt * 64 + warp * 16 + (lane >> 2);

    uint32_t qf[4][4];
    bool qloaded = false;

#pragma unroll 1
    for (int kt = 0; kt <= qt; ++kt) {
        const int s = kt & 1;
        asm volatile("cp.async.wait_group 0;\n" ::);
        __syncthreads();
        if (kt + 1 <= qt)
            at_load_kv(sb, s ^ 1, gbase, kt + 1, tid);

        if (!qloaded) {
            qloaded = true;
#pragma unroll
            for (int k16 = 0; k16 < 4; ++k16) {
                int row = warp * 16 + (lane & 15);
                uint32_t off = (uint32_t)(row * AT_STRIDE + (lane >> 4) * 8 + k16 * 16) * 2;
                ldsm4(qf[k16], sb + off);
            }
        }

        const uint32_t kvb = sb + (AT_KVBASE + s * AT_STAGE) * 2;

        // ---- S = Q @ K^T (single fp16) ----
        float sAcc[8][4];
#pragma unroll
        for (int nt = 0; nt < 8; ++nt)
#pragma unroll
            for (int c = 0; c < 4; ++c) sAcc[nt][c] = 0.0f;

#pragma unroll
        for (int k16 = 0; k16 < 4; ++k16) {
#pragma unroll
            for (int np = 0; np < 4; ++np) {
                int krow = np * 16 + (lane & 7) + ((lane >> 4) << 3);
                uint32_t off = (uint32_t)(krow * AT_STRIDE + ((lane >> 3) & 1) * 8 + k16 * 16) * 2;
                uint32_t kf[4];
                ldsm4(kf, kvb + off);
                mma16816f(sAcc[np * 2],     qf[k16], kf);
                mma16816f(sAcc[np * 2 + 1], qf[k16], kf + 2);
            }
        }

        // ---- scale + causal mask ----
        const float invs = 0.125f;
        if (kt == qt) {
#pragma unroll
            for (int nt = 0; nt < 8; ++nt) {
                const int colb = kt * 64 + nt * 8 + (lane & 3) * 2;
#pragma unroll
                for (int c = 0; c < 4; ++c) {
                    const int col = colb + (c & 1);
                    const int row = row0g + ((c >> 1) << 3);
                    sAcc[nt][c] = (col <= row) ? sAcc[nt][c] * invs : -1e30f;
                }
            }
        } else {
#pragma unroll
            for (int nt = 0; nt < 8; ++nt)
#pragma unroll
                for (int c = 0; c < 4; ++c) sAcc[nt][c] *= invs;
        }

        // ---- online softmax ----
        float mx0 = -1e30f, mx1 = -1e30f;
#pragma unroll
        for (int nt = 0; nt < 8; ++nt) {
            mx0 = fmaxf(mx0, fmaxf(sAcc[nt][0], sAcc[nt][1]));
            mx1 = fmaxf(mx1, fmaxf(sAcc[nt][2], sAcc[nt][3]));
        }
        mx0 = fmaxf(mx0, __shfl_xor_sync(0xffffffffu, mx0, 1));
        mx0 = fmaxf(mx0, __shfl_xor_sync(0xffffffffu, mx0, 2));
        mx1 = fmaxf(mx1, __shfl_xor_sync(0xffffffffu, mx1, 1));
        mx1 = fmaxf(mx1, __shfl_xor_sync(0xffffffffu, mx1, 2));

        const float mn0 = fmaxf(m0, mx0);
        const float mn1 = fmaxf(m1, mx1);
        const float fac0 = fexp(m0 - mn0);
        const float fac1 = fexp(m1 - mn1);
        m0 = mn0; m1 = mn1;

        float sum0 = 0.0f, sum1 = 0.0f;
#pragma unroll
        for (int nt = 0; nt < 8; ++nt) {
            sAcc[nt][0] = fexp(sAcc[nt][0] - m0);
            sAcc[nt][1] = fexp(sAcc[nt][1] - m0);
            sAcc[nt][2] = fexp(sAcc[nt][2] - m1);
            sAcc[nt][3] = fexp(sAcc[nt][3] - m1);
            sum0 += sAcc[nt][0] + sAcc[nt][1];
            sum1 += sAcc[nt][2] + sAcc[nt][3];
        }
        sum0 += __shfl_xor_sync(0xffffffffu, sum0, 1);
        sum0 += __shfl_xor_sync(0xffffffffu, sum0, 2);
        sum1 += __shfl_xor_sync(0xffffffffu, sum1, 1);
        sum1 += __shfl_xor_sync(0xffffffffu, sum1, 2);
        l0 = l0 * fac0 + sum0;
        l1 = l1 * fac1 + sum1;

#pragma unroll
        for (int nt = 0; nt < 8; ++nt) {
            oAcc[nt][0] *= fac0; oAcc[nt][1] *= fac0;
            oAcc[nt][2] *= fac1; oAcc[nt][3] *= fac1;
        }

        // ---- O += P @ V (single fp16) ----
        const uint32_t vb = kvb + AT_TILE * 2;
#pragma unroll
        for (int c16 = 0; c16 < 4; ++c16) {
            uint32_t pa[4];
#pragma unroll
            for (int half = 0; half < 2; ++half) {
                const float* pv = sAcc[2 * c16 + half];
                __half2 p01 = __floats2half2_rn(pv[0], pv[1]);
                __half2 p23 = __floats2half2_rn(pv[2], pv[3]);
                pa[half * 2 + 0] = *(uint32_t*)&p01;
                pa[half * 2 + 1] = *(uint32_t*)&p23;
            }
#pragma unroll
            for (int np = 0; np < 4; ++np) {
                int vrow = c16 * 16 + (lane & 7) + 8 * ((lane >> 3) & 1);
                int vcol = np * 16 + 8 * (lane >> 4);
                uint32_t off = (uint32_t)(vrow * AT_STRIDE + vcol) * 2;
                uint32_t vf[4];
                ldsm4t(vf, vb + off);
                mma16816f(oAcc[np * 2],     pa, vf);
                mma16816f(oAcc[np * 2 + 1], pa, vf + 2);
            }
        }
    }

    // ---- epilogue ----
    const float inv0 = 1.0f / l0;
    const float inv1 = 1.0f / l1;
    const int b = bh >> 4;
    const int h = bh & 15;
#pragma unroll
    for (int rr = 0; rr < 2; ++rr) {
        const int t = qt * 64 + warp * 16 + (lane >> 2) + rr * 8;
        const float inv = rr ? inv1 : inv0;
        size_t rowoff = AOFF + ((size_t)b * T_ + t) * D_ + h * DK_ + (lane & 3) * 2;
#pragma unroll
        for (int nt = 0; nt < 8; ++nt) {
            *(__half2*)&g_af[rowoff + nt * 8] = __floats2half2_rn(
                oAcc[nt][rr * 2] * inv, oAcc[nt][rr * 2 + 1] * inv);
        }
    }
}

// ---------------------------------------------------------------------------
// Launch
// ---------------------------------------------------------------------------
extern "C" void kernel_launch(void* const* d_in, const int* in_sizes, int n_in,
                              void* d_out, int out_size)
{
    (void)in_sizes; (void)n_in; (void)out_size;
    const float* x  = (const float*)d_in[0];
    const float* Wq = (const float*)d_in[2];
    const float* Wk = (const float*)d_in[3];
    const float* Wv = (const float*)d_in[4];
    const float* Wo = (const float*)d_in[5];
    const float* bq = (const float*)d_in[6];
    const float* bk = (const float*)d_in[7];
    const float* bv = (const float*)d_in[8];
    const float* bo = (const float*)d_in[9];
    float* out = (float*)d_out;

    conv_all<<<NBX + 4 * NBW, 256>>>(x, Wq, Wk, Wv, Wo);

    const int gemm_smem = G_NSTG * STAGE_B;   // 92160
    cudaFuncSetAttribute(mma_gemm<1>, cudaFuncAttributeMaxDynamicSharedMemorySize, gemm_smem);
    cudaFuncSetAttribute(mma_gemm<0>, cudaFuncAttributeMaxDynamicSharedMemorySize, gemm_smem);
    cudaFuncSetAttribute(attn_kernel, cudaFuncAttributeMaxDynamicSharedMemorySize, AT_SMEM_BYTES);

    // Fused QKV projection: grid (3*8, 64)
    mma_gemm<1><<<dim3(24, M_ / 128), 256, gemm_smem>>>(bq, bk, bv, nullptr);

    // Attention: 64 query rows per CTA, 2 CTAs/SM
    attn_kernel<<<dim3(T_ / 64, B_ * H_), 128, AT_SMEM_BYTES>>>();

    // Output projection
    mma_gemm<0><<<dim3(N_ / 128, M_ / 128), 256, gemm_smem>>>(bo, nullptr, nullptr, out);
}

// round 12
// speedup vs baseline: 3.5786x; 1.4106x over previous
#include <cuda_runtime.h>
#include <cuda_fp16.h>
#include <math.h>
#include <stdint.h>

// Problem constants
constexpr int B_ = 4;
constexpr int T_ = 2048;
constexpr int D_ = 1024;
constexpr int H_ = 16;
constexpr int DK_ = 64;
constexpr int M_ = B_ * T_;   // 8192
constexpr int N_ = D_;        // 1024
constexpr int K_ = D_;        // 1024

// fp16 arenas.
constexpr size_t XOFF = 0;
constexpr size_t AOFF = (size_t)M_ * K_;
constexpr size_t AF_SZ = AOFF + (size_t)M_ * D_;
__device__ __half g_af[AF_SZ];
__device__ __half g_wh[4ull * N_ * K_];

// Q/K/V single fp16, layout [B*H, T, DK]
constexpr size_t QKV_SZ = (size_t)B_ * H_ * T_ * DK_;
__device__ __half g_qf[QKV_SZ];
__device__ __half g_kf[QKV_SZ];
__device__ __half g_vf[QKV_SZ];

// ---------------------------------------------------------------------------
// Fused converter: x and W0..W3 -> single fp16
// ---------------------------------------------------------------------------
constexpr int NBX = (M_ * K_ / 8) / 256;   // 4096
constexpr int NBW = (N_ * K_ / 8) / 256;   // 512

__global__ void conv_all(const float* __restrict__ x,
                         const float* __restrict__ w0, const float* __restrict__ w1,
                         const float* __restrict__ w2, const float* __restrict__ w3)
{
    const int blk = blockIdx.x;
    const float* src;
    __half* dst;
    int i;
    if (blk < NBX) {
        src = x; dst = g_af;
        i = blk * 256 + threadIdx.x;
    } else {
        const int r = blk - NBX;
        const int w = r / NBW;
        src = (w == 0) ? w0 : (w == 1) ? w1 : (w == 2) ? w2 : w3;
        dst = g_wh + (size_t)w * N_ * K_;
        i = (r % NBW) * 256 + threadIdx.x;
    }
    const float4* p4 = (const float4*)src;
    float4 a = p4[2 * i], b = p4[2 * i + 1];
    __half2 h[4];
    h[0] = __floats2half2_rn(a.x, a.y);
    h[1] = __floats2half2_rn(a.z, a.w);
    h[2] = __floats2half2_rn(b.x, b.y);
    h[3] = __floats2half2_rn(b.z, b.w);
    *(uint4*)(dst + (size_t)i * 8) = *(uint4*)h;
}

// ---------------------------------------------------------------------------
// MMA helpers
// ---------------------------------------------------------------------------
__device__ __forceinline__ void cp16(uint32_t dst, const void* src)
{
    asm volatile("cp.async.cg.shared.global [%0],[%1],16;\n" :: "r"(dst), "l"(src));
}
__device__ __forceinline__ void ldsm4(uint32_t* r, uint32_t addr)
{
    asm volatile("ldmatrix.sync.aligned.m8n8.x4.shared.b16 {%0,%1,%2,%3},[%4];"
                 : "=r"(r[0]), "=r"(r[1]), "=r"(r[2]), "=r"(r[3]) : "r"(addr));
}
__device__ __forceinline__ void ldsm4t(uint32_t* r, uint32_t addr)
{
    asm volatile("ldmatrix.sync.aligned.m8n8.x4.trans.shared.b16 {%0,%1,%2,%3},[%4];"
                 : "=r"(r[0]), "=r"(r[1]), "=r"(r[2]), "=r"(r[3]) : "r"(addr));
}
__device__ __forceinline__ void mma16816f(float* c, const uint32_t* a, const uint32_t* b)
{
    asm volatile(
        "mma.sync.aligned.m16n8k16.row.col.f32.f16.f16.f32 "
        "{%0,%1,%2,%3},{%4,%5,%6,%7},{%8,%9},{%0,%1,%2,%3};"
        : "+f"(c[0]), "+f"(c[1]), "+f"(c[2]), "+f"(c[3])
        : "r"(a[0]), "r"(a[1]), "r"(a[2]), "r"(a[3]), "r"(b[0]), "r"(b[1]));
}

// Fast exp: degree-5 poly for 2^f + exponent splice. x <= 0 expected.
__device__ __forceinline__ float fexp(float x)
{
    float t = fmaxf(x * 1.4426950408889634f, -126.0f);
    int n = __float2int_rn(t);
    float f = t - (float)n;
    float p = 1.33336621e-3f;
    p = fmaf(p, f, 9.61812910e-3f);
    p = fmaf(p, f, 5.55041087e-2f);
    p = fmaf(p, f, 2.40226507e-1f);
    p = fmaf(p, f, 6.93147182e-1f);
    p = fmaf(p, f, 1.0f);
    return __int_as_float(__float_as_int(p) + (n << 23));
}

// ---------------------------------------------------------------------------
// Tensor-core GEMM: C = A @ W^T + bias. Single fp16 both operands, 1 MMA.
// 3-stage cp.async pipeline, one __syncthreads per k-tile.
// smem stage: A (10240 B) | Wh (10240) = 20480 B.
// ---------------------------------------------------------------------------
constexpr int STAGE_B = 20480;
constexpr int G_NSTG = 3;

__device__ __forceinline__ void stage_load(
    const __half* Af, const __half* Wh,
    uint32_t sb, int bm, int bn, int k0, int tid)
{
#pragma unroll
    for (int i = 0; i < 4; ++i) {
        const int arr = i >> 1;
        const int within = tid + (i & 1) * 256;
        const int row = within >> 2;
        const int cc = within & 3;
        uint32_t so = (uint32_t)(arr * 10240 + row * 80 + cc * 16);
        const __half* src = (arr == 0) ? Af + (size_t)(bm + row) * K_ + k0 + cc * 8
                                       : Wh + (size_t)(bn + row) * K_ + k0 + cc * 8;
        cp16(sb + so, src);
    }
    asm volatile("cp.async.commit_group;\n" ::);
}

template<int QKV>
__global__ __launch_bounds__(256, 2)
void mma_gemm(const float* __restrict__ b0p, const float* __restrict__ b1p,
              const float* __restrict__ b2p, float* __restrict__ C)
{
    extern __shared__ __half smem_raw[];
    const int tid = threadIdx.x;
    const int lane = tid & 31;
    const int warp = tid >> 5;
    const int wm = warp >> 1;
    const int wn = warp & 1;
    const int bm = blockIdx.y * 128;
    const int wsel = QKV ? (blockIdx.x >> 3) : 0;
    const int bn = (QKV ? (blockIdx.x & 7) : blockIdx.x) * 128;

    const __half* Af = g_af + (QKV ? XOFF : AOFF);
    const __half* Wh = g_wh + (size_t)(QKV ? wsel : 3) * N_ * K_;
    const float* bias = QKV ? (wsel == 0 ? b0p : wsel == 1 ? b1p : b2p) : b0p;

    uint32_t sbase = (uint32_t)__cvta_generic_to_shared(smem_raw);

    float acc[2][8][4];
#pragma unroll
    for (int mi = 0; mi < 2; ++mi)
#pragma unroll
        for (int ni = 0; ni < 8; ++ni)
#pragma unroll
            for (int r = 0; r < 4; ++r) acc[mi][ni][r] = 0.0f;

    constexpr int NT = K_ / 32;

    stage_load(Af, Wh, sbase, bm, bn, 0, tid);
    stage_load(Af, Wh, sbase + STAGE_B, bm, bn, 32, tid);

#pragma unroll 1
    for (int kt = 0; kt < NT; ++kt) {
        const int s = kt % G_NSTG;
        if (kt + 1 < NT) {
            asm volatile("cp.async.wait_group 1;\n" ::);
        } else {
            asm volatile("cp.async.wait_group 0;\n" ::);
        }
        __syncthreads();
        if (kt + 2 < NT)
            stage_load(Af, Wh, sbase + ((kt + 2) % G_NSTG) * STAGE_B,
                       bm, bn, (kt + 2) * 32, tid);

        const uint32_t sb = sbase + s * STAGE_B;
#pragma unroll
        for (int k16 = 0; k16 < 2; ++k16) {
            uint32_t af[2][4];
#pragma unroll
            for (int mi = 0; mi < 2; ++mi) {
                int row = wm * 32 + mi * 16 + (lane & 15);
                uint32_t off = (uint32_t)(row * 80 + ((lane >> 4) * 8 + k16 * 16) * 2);
                ldsm4(af[mi], sb + off);
            }
#pragma unroll
            for (int nq = 0; nq < 4; ++nq) {
                int wrow = wn * 64 + nq * 16 + (lane & 7) + ((lane >> 4) << 3);
                uint32_t off = (uint32_t)(wrow * 80 + (((lane >> 3) & 1) * 8 + k16 * 16) * 2);
                uint32_t wh[4];
                ldsm4(wh, sb + 10240 + off);
                mma16816f(acc[0][nq * 2],     af[0], wh);
                mma16816f(acc[0][nq * 2 + 1], af[0], wh + 2);
                mma16816f(acc[1][nq * 2],     af[1], wh);
                mma16816f(acc[1][nq * 2 + 1], af[1], wh + 2);
            }
        }
    }

#pragma unroll
    for (int mi = 0; mi < 2; ++mi) {
#pragma unroll
        for (int ni = 0; ni < 8; ++ni) {
            const int r0 = bm + wm * 32 + mi * 16 + (lane >> 2);
            const int c0 = bn + wn * 64 + ni * 8 + (lane & 3) * 2;
            const float b0 = bias[c0];
            const float b1 = bias[c0 + 1];
            float2 v01 = make_float2(acc[mi][ni][0] + b0, acc[mi][ni][1] + b1);
            float2 v23 = make_float2(acc[mi][ni][2] + b0, acc[mi][ni][3] + b1);
            if (!QKV) {
                *(float2*)&C[(size_t)r0 * N_ + c0] = v01;
                *(float2*)&C[(size_t)(r0 + 8) * N_ + c0] = v23;
            } else {
                __half* dst = (wsel == 0) ? g_qf : (wsel == 1) ? g_kf : g_vf;
                const int h = c0 >> 6;
                const int d = c0 & (DK_ - 1);
#pragma unroll
                for (int rr = 0; rr < 2; ++rr) {
                    const int row = r0 + rr * 8;
                    const int b = row >> 11, t = row & (T_ - 1);
                    const float x0 = rr ? v23.x : v01.x;
                    const float x1 = rr ? v23.y : v01.y;
                    size_t off = (((size_t)b * H_ + h) * T_ + t) * DK_ + d;
                    *(__half2*)&dst[off] = __floats2half2_rn(x0, x1);
                }
            }
        }
    }
}

// ---------------------------------------------------------------------------
// Flash attention: single fp16 QK^T and PV. Causal, online softmax.
// One __syncthreads per KV tile. 128 threads, 64 query rows. 2 CTAs/SM.
// ---------------------------------------------------------------------------
constexpr int AT_STRIDE = 72;
constexpr int AT_TILE = 64 * AT_STRIDE;
constexpr int AT_KVBASE = AT_TILE;                          // after Qf
constexpr int AT_STAGE = 2 * AT_TILE;                       // Kf,Vf
constexpr int AT_SMEM_ELEMS = AT_KVBASE + 2 * AT_STAGE;     // 23040
constexpr int AT_SMEM_BYTES = AT_SMEM_ELEMS * 2;            // 46080

__device__ __forceinline__ void at_load_kv(uint32_t sb, int stage, size_t gbase, int kt, int tid)
{
    uint32_t stbase = sb + (AT_KVBASE + stage * AT_STAGE) * 2;
    const __half* srcs[2] = {g_kf, g_vf};
#pragma unroll
    for (int i = 0; i < 8; ++i) {
        const int arr = i >> 2;
        const int within = (tid + (i & 3) * 128) & 511;
        const int row = within >> 3;
        const int cc = within & 7;
        uint32_t so = stbase + (arr * AT_TILE + row * AT_STRIDE + cc * 8) * 2;
        cp16(so, srcs[arr] + gbase + (size_t)(kt * 64 + row) * DK_ + cc * 8);
    }
    asm volatile("cp.async.commit_group;\n" ::);
}

__global__ __launch_bounds__(128, 2)
void attn_kernel()
{
    extern __shared__ __half at_sm[];
    uint32_t sb = (uint32_t)__cvta_generic_to_shared(at_sm);

    const int tid = threadIdx.x;
    const int lane = tid & 31;
    const int warp = tid >> 5;

    const int qt = (int)gridDim.x - 1 - (int)blockIdx.x;
    const int bh = blockIdx.y;
    const size_t gbase = (size_t)bh * T_ * DK_;

#pragma unroll
    for (int i = 0; i < 4; ++i) {
        const int within = tid + i * 128;
        const int row = within >> 3;
        const int cc = within & 7;
        uint32_t so = sb + (row * AT_STRIDE + cc * 8) * 2;
        cp16(so, g_qf + gbase + (size_t)(qt * 64 + row) * DK_ + cc * 8);
    }
    at_load_kv(sb, 0, gbase, 0, tid);

    float oAcc[8][4];
#pragma unroll
    for (int nt = 0; nt < 8; ++nt)
#pragma unroll
        for (int c = 0; c < 4; ++c) oAcc[nt][c] = 0.0f;

    float m0 = -1e30f, m1 = -1e30f, l0 = 0.0f, l1 = 0.0f;
    const int row0g = qt * 64 + warp * 16 + (lane >> 2);

    uint32_t qf[4][4];
    bool qloaded = false;

#pragma unroll 1
    for (int kt = 0; kt <= qt; ++kt) {
        const int s = kt & 1;
        asm volatile("cp.async.wait_group 0;\n" ::);
        __syncthreads();
        if (kt + 1 <= qt)
            at_load_kv(sb, s ^ 1, gbase, kt + 1, tid);

        if (!qloaded) {
            qloaded = true;
#pragma unroll
            for (int k16 = 0; k16 < 4; ++k16) {
                int row = warp * 16 + (lane & 15);
                uint32_t off = (uint32_t)(row * AT_STRIDE + (lane >> 4) * 8 + k16 * 16) * 2;
                ldsm4(qf[k16], sb + off);
            }
        }

        const uint32_t kvb = sb + (AT_KVBASE + s * AT_STAGE) * 2;

        float sAcc[8][4];
#pragma unroll
        for (int nt = 0; nt < 8; ++nt)
#pragma unroll
            for (int c = 0; c < 4; ++c) sAcc[nt][c] = 0.0f;

#pragma unroll
        for (int k16 = 0; k16 < 4; ++k16) {
#pragma unroll
            for (int np = 0; np < 4; ++np) {
                int krow = np * 16 + (lane & 7) + ((lane >> 4) << 3);
                uint32_t off = (uint32_t)(krow * AT_STRIDE + ((lane >> 3) & 1) * 8 + k16 * 16) * 2;
                uint32_t kf[4];
                ldsm4(kf, kvb + off);
                mma16816f(sAcc[np * 2],     qf[k16], kf);
                mma16816f(sAcc[np * 2 + 1], qf[k16], kf + 2);
            }
        }

        const float invs = 0.125f;
        if (kt == qt) {
#pragma unroll
            for (int nt = 0; nt < 8; ++nt) {
                const int colb = kt * 64 + nt * 8 + (lane & 3) * 2;
#pragma unroll
                for (int c = 0; c < 4; ++c) {
                    const int col = colb + (c & 1);
                    const int row = row0g + ((c >> 1) << 3);
                    sAcc[nt][c] = (col <= row) ? sAcc[nt][c] * invs : -1e30f;
                }
            }
        } else {
#pragma unroll
            for (int nt = 0; nt < 8; ++nt)
#pragma unroll
                for (int c = 0; c < 4; ++c) sAcc[nt][c] *= invs;
        }

        float mx0 = -1e30f, mx1 = -1e30f;
#pragma unroll
        for (int nt = 0; nt < 8; ++nt) {
            mx0 = fmaxf(mx0, fmaxf(sAcc[nt][0], sAcc[nt][1]));
            mx1 = fmaxf(mx1, fmaxf(sAcc[nt][2], sAcc[nt][3]));
        }
        mx0 = fmaxf(mx0, __shfl_xor_sync(0xffffffffu, mx0, 1));
        mx0 = fmaxf(mx0, __shfl_xor_sync(0xffffffffu, mx0, 2));
        mx1 = fmaxf(mx1, __shfl_xor_sync(0xffffffffu, mx1, 1));
        mx1 = fmaxf(mx1, __shfl_xor_sync(0xffffffffu, mx1, 2));

        const float mn0 = fmaxf(m0, mx0);
        const float mn1 = fmaxf(m1, mx1);
        const float fac0 = fexp(m0 - mn0);
        const float fac1 = fexp(m1 - mn1);
        m0 = mn0; m1 = mn1;

        float sum0 = 0.0f, sum1 = 0.0f;
#pragma unroll
        for (int nt = 0; nt < 8; ++nt) {
            sAcc[nt][0] = fexp(sAcc[nt][0] - m0);
            sAcc[nt][1] = fexp(sAcc[nt][1] - m0);
            sAcc[nt][2] = fexp(sAcc[nt][2] - m1);
            sAcc[nt][3] = fexp(sAcc[nt][3] - m1);
            sum0 += sAcc[nt][0] + sAcc[nt][1];
            sum1 += sAcc[nt][2] + sAcc[nt][3];
        }
        sum0 += __shfl_xor_sync(0xffffffffu, sum0, 1);
        sum0 += __shfl_xor_sync(0xffffffffu, sum0, 2);
        sum1 += __shfl_xor_sync(0xffffffffu, sum1, 1);
        sum1 += __shfl_xor_sync(0xffffffffu, sum1, 2);
        l0 = l0 * fac0 + sum0;
        l1 = l1 * fac1 + sum1;

#pragma unroll
        for (int nt = 0; nt < 8; ++nt) {
            oAcc[nt][0] *= fac0; oAcc[nt][1] *= fac0;
            oAcc[nt][2] *= fac1; oAcc[nt][3] *= fac1;
        }

        const uint32_t vb = kvb + AT_TILE * 2;
#pragma unroll
        for (int c16 = 0; c16 < 4; ++c16) {
            uint32_t pa[4];
#pragma unroll
            for (int half = 0; half < 2; ++half) {
                const float* pv = sAcc[2 * c16 + half];
                __half2 p01 = __floats2half2_rn(pv[0], pv[1]);
                __half2 p23 = __floats2half2_rn(pv[2], pv[3]);
                pa[half * 2 + 0] = *(uint32_t*)&p01;
                pa[half * 2 + 1] = *(uint32_t*)&p23;
            }
#pragma unroll
            for (int np = 0; np < 4; ++np) {
                int vrow = c16 * 16 + (lane & 7) + 8 * ((lane >> 3) & 1);
                int vcol = np * 16 + 8 * (lane >> 4);
                uint32_t off = (uint32_t)(vrow * AT_STRIDE + vcol) * 2;
                uint32_t vf[4];
                ldsm4t(vf, vb + off);
                mma16816f(oAcc[np * 2],     pa, vf);
                mma16816f(oAcc[np * 2 + 1], pa, vf + 2);
            }
        }
    }

    const float inv0 = 1.0f / l0;
    const float inv1 = 1.0f / l1;
    const int b = bh >> 4;
    const int h = bh & 15;
#pragma unroll
    for (int rr = 0; rr < 2; ++rr) {
        const int t = qt * 64 + warp * 16 + (lane >> 2) + rr * 8;
        const float inv = rr ? inv1 : inv0;
        size_t rowoff = AOFF + ((size_t)b * T_ + t) * D_ + h * DK_ + (lane & 3) * 2;
#pragma unroll
        for (int nt = 0; nt < 8; ++nt) {
            *(__half2*)&g_af[rowoff + nt * 8] = __floats2half2_rn(
                oAcc[nt][rr * 2] * inv, oAcc[nt][rr * 2 + 1] * inv);
        }
    }
}

// ---------------------------------------------------------------------------
// Launch
// ---------------------------------------------------------------------------
extern "C" void kernel_launch(void* const* d_in, const int* in_sizes, int n_in,
                              void* d_out, int out_size)
{
    (void)in_sizes; (void)n_in; (void)out_size;
    const float* x  = (const float*)d_in[0];
    const float* Wq = (const float*)d_in[2];
    const float* Wk = (const float*)d_in[3];
    const float* Wv = (const float*)d_in[4];
    const float* Wo = (const float*)d_in[5];
    const float* bq = (const float*)d_in[6];
    const float* bk = (const float*)d_in[7];
    const float* bv = (const float*)d_in[8];
    const float* bo = (const float*)d_in[9];
    float* out = (float*)d_out;

    conv_all<<<NBX + 4 * NBW, 256>>>(x, Wq, Wk, Wv, Wo);

    const int gemm_smem = G_NSTG * STAGE_B;   // 61440
    cudaFuncSetAttribute(mma_gemm<1>, cudaFuncAttributeMaxDynamicSharedMemorySize, gemm_smem);
    cudaFuncSetAttribute(mma_gemm<0>, cudaFuncAttributeMaxDynamicSharedMemorySize, gemm_smem);
    cudaFuncSetAttribute(attn_kernel, cudaFuncAttributeMaxDynamicSharedMemorySize, AT_SMEM_BYTES);

    // Fused QKV projection: grid (3*8, 64)
    mma_gemm<1><<<dim3(24, M_ / 128), 256, gemm_smem>>>(bq, bk, bv, nullptr);

    // Attention: 64 query rows per CTA, 2 CTAs/SM
    attn_kernel<<<dim3(T_ / 64, B_ * H_), 128, AT_SMEM_BYTES>>>();

    // Output projection
    mma_gemm<0><<<dim3(N_ / 128, M_ / 128), 256, gemm_smem>>>(bo, nullptr, nullptr, out);
}

// round 14
// speedup vs baseline: 3.6841x; 1.0295x over previous
#include <cuda_runtime.h>
#include <cuda_fp16.h>
#include <math.h>
#include <stdint.h>

// Problem constants
constexpr int B_ = 4;
constexpr int T_ = 2048;
constexpr int D_ = 1024;
constexpr int H_ = 16;
constexpr int DK_ = 64;
constexpr int M_ = B_ * T_;   // 8192
constexpr int N_ = D_;        // 1024
constexpr int K_ = D_;        // 1024

// fp16 arenas.
constexpr size_t XOFF = 0;
constexpr size_t AOFF = (size_t)M_ * K_;
constexpr size_t AF_SZ = AOFF + (size_t)M_ * D_;
__device__ __half g_af[AF_SZ];
__device__ __half g_wh[4ull * N_ * K_];

// Q/K/V single fp16, layout [B*H, T, DK]
constexpr size_t QKV_SZ = (size_t)B_ * H_ * T_ * DK_;
__device__ __half g_qf[QKV_SZ];
__device__ __half g_kf[QKV_SZ];
__device__ __half g_vf[QKV_SZ];

// ---------------------------------------------------------------------------
// Fused converter: x and W0..W3 -> single fp16
// ---------------------------------------------------------------------------
constexpr int NBX = (M_ * K_ / 8) / 256;   // 4096
constexpr int NBW = (N_ * K_ / 8) / 256;   // 512

__global__ void conv_all(const float* __restrict__ x,
                         const float* __restrict__ w0, const float* __restrict__ w1,
                         const float* __restrict__ w2, const float* __restrict__ w3)
{
    const int blk = blockIdx.x;
    const float* src;
    __half* dst;
    int i;
    if (blk < NBX) {
        src = x; dst = g_af;
        i = blk * 256 + threadIdx.x;
    } else {
        const int r = blk - NBX;
        const int w = r / NBW;
        src = (w == 0) ? w0 : (w == 1) ? w1 : (w == 2) ? w2 : w3;
        dst = g_wh + (size_t)w * N_ * K_;
        i = (r % NBW) * 256 + threadIdx.x;
    }
    const float4* p4 = (const float4*)src;
    float4 a = p4[2 * i], b = p4[2 * i + 1];
    __half2 h[4];
    h[0] = __floats2half2_rn(a.x, a.y);
    h[1] = __floats2half2_rn(a.z, a.w);
    h[2] = __floats2half2_rn(b.x, b.y);
    h[3] = __floats2half2_rn(b.z, b.w);
    *(uint4*)(dst + (size_t)i * 8) = *(uint4*)h;
}

// ---------------------------------------------------------------------------
// MMA helpers
// ---------------------------------------------------------------------------
__device__ __forceinline__ void cp16(uint32_t dst, const void* src)
{
    asm volatile("cp.async.cg.shared.global [%0],[%1],16;\n" :: "r"(dst), "l"(src));
}
__device__ __forceinline__ void ldsm4(uint32_t* r, uint32_t addr)
{
    asm volatile("ldmatrix.sync.aligned.m8n8.x4.shared.b16 {%0,%1,%2,%3},[%4];"
                 : "=r"(r[0]), "=r"(r[1]), "=r"(r[2]), "=r"(r[3]) : "r"(addr));
}
__device__ __forceinline__ void ldsm4t(uint32_t* r, uint32_t addr)
{
    asm volatile("ldmatrix.sync.aligned.m8n8.x4.trans.shared.b16 {%0,%1,%2,%3},[%4];"
                 : "=r"(r[0]), "=r"(r[1]), "=r"(r[2]), "=r"(r[3]) : "r"(addr));
}
__device__ __forceinline__ void mma16816f(float* c, const uint32_t* a, const uint32_t* b)
{
    asm volatile(
        "mma.sync.aligned.m16n8k16.row.col.f32.f16.f16.f32 "
        "{%0,%1,%2,%3},{%4,%5,%6,%7},{%8,%9},{%0,%1,%2,%3};"
        : "+f"(c[0]), "+f"(c[1]), "+f"(c[2]), "+f"(c[3])
        : "r"(a[0]), "r"(a[1]), "r"(a[2]), "r"(a[3]), "r"(b[0]), "r"(b[1]));
}

// Fast exp: degree-5 poly for 2^f + exponent splice. x <= 0 expected.
__device__ __forceinline__ float fexp(float x)
{
    float t = fmaxf(x * 1.4426950408889634f, -126.0f);
    int n = __float2int_rn(t);
    float f = t - (float)n;
    float p = 1.33336621e-3f;
    p = fmaf(p, f, 9.61812910e-3f);
    p = fmaf(p, f, 5.55041087e-2f);
    p = fmaf(p, f, 2.40226507e-1f);
    p = fmaf(p, f, 6.93147182e-1f);
    p = fmaf(p, f, 1.0f);
    return __int_as_float(__float_as_int(p) + (n << 23));
}

// ---------------------------------------------------------------------------
// Tensor-core GEMM: C = A @ W^T + bias. Single fp16 both operands, 1 MMA.
// 3-stage cp.async pipeline, W-fragment double buffering (prefetch nq+1).
// nq stride in smem: 16 rows * 80 B = 1280 B.
// ---------------------------------------------------------------------------
constexpr int STAGE_B = 20480;
constexpr int G_NSTG = 3;

__device__ __forceinline__ void stage_load(
    const __half* Af, const __half* Wh,
    uint32_t sb, int bm, int bn, int k0, int tid)
{
#pragma unroll
    for (int i = 0; i < 4; ++i) {
        const int arr = i >> 1;
        const int within = tid + (i & 1) * 256;
        const int row = within >> 2;
        const int cc = within & 3;
        uint32_t so = (uint32_t)(arr * 10240 + row * 80 + cc * 16);
        const __half* src = (arr == 0) ? Af + (size_t)(bm + row) * K_ + k0 + cc * 8
                                       : Wh + (size_t)(bn + row) * K_ + k0 + cc * 8;
        cp16(sb + so, src);
    }
    asm volatile("cp.async.commit_group;\n" ::);
}

template<int QKV>
__global__ __launch_bounds__(256, 2)
void mma_gemm(const float* __restrict__ b0p, const float* __restrict__ b1p,
              const float* __restrict__ b2p, float* __restrict__ C)
{
    extern __shared__ __half smem_raw[];
    const int tid = threadIdx.x;
    const int lane = tid & 31;
    const int warp = tid >> 5;
    const int wm = warp >> 1;
    const int wn = warp & 1;
    const int bm = blockIdx.y * 128;
    const int wsel = QKV ? (blockIdx.x >> 3) : 0;
    const int bn = (QKV ? (blockIdx.x & 7) : blockIdx.x) * 128;

    const __half* Af = g_af + (QKV ? XOFF : AOFF);
    const __half* Wh = g_wh + (size_t)(QKV ? wsel : 3) * N_ * K_;
    const float* bias = QKV ? (wsel == 0 ? b0p : wsel == 1 ? b1p : b2p) : b0p;

    uint32_t sbase = (uint32_t)__cvta_generic_to_shared(smem_raw);

    float acc[2][8][4];
#pragma unroll
    for (int mi = 0; mi < 2; ++mi)
#pragma unroll
        for (int ni = 0; ni < 8; ++ni)
#pragma unroll
            for (int r = 0; r < 4; ++r) acc[mi][ni][r] = 0.0f;

    constexpr int NT = K_ / 32;

    stage_load(Af, Wh, sbase, bm, bn, 0, tid);
    stage_load(Af, Wh, sbase + STAGE_B, bm, bn, 32, tid);

#pragma unroll 1
    for (int kt = 0; kt < NT; ++kt) {
        const int s = kt % G_NSTG;
        if (kt + 1 < NT) {
            asm volatile("cp.async.wait_group 1;\n" ::);
        } else {
            asm volatile("cp.async.wait_group 0;\n" ::);
        }
        __syncthreads();
        if (kt + 2 < NT)
            stage_load(Af, Wh, sbase + ((kt + 2) % G_NSTG) * STAGE_B,
                       bm, bn, (kt + 2) * 32, tid);

        const uint32_t sb = sbase + s * STAGE_B;
#pragma unroll
        for (int k16 = 0; k16 < 2; ++k16) {
            // W-fragment base address for this k16 (affine in nq: +1280 B per nq)
            const uint32_t wbase = sb + 10240 +
                (uint32_t)(((wn * 64 + (lane & 7) + ((lane >> 4) << 3)) * 80 +
                            (((lane >> 3) & 1) * 8 + k16 * 16) * 2));
            uint32_t af[2][4];
#pragma unroll
            for (int mi = 0; mi < 2; ++mi) {
                int row = wm * 32 + mi * 16 + (lane & 15);
                uint32_t off = (uint32_t)(row * 80 + ((lane >> 4) * 8 + k16 * 16) * 2);
                ldsm4(af[mi], sb + off);
            }
            uint32_t wh[2][4];
            ldsm4(wh[0], wbase);
#pragma unroll
            for (int nq = 0; nq < 4; ++nq) {
                if (nq < 3) ldsm4(wh[(nq + 1) & 1], wbase + (uint32_t)(nq + 1) * 1280u);
                const uint32_t* W = wh[nq & 1];
                mma16816f(acc[0][nq * 2],     af[0], W);
                mma16816f(acc[0][nq * 2 + 1], af[0], W + 2);
                mma16816f(acc[1][nq * 2],     af[1], W);
                mma16816f(acc[1][nq * 2 + 1], af[1], W + 2);
            }
        }
    }

#pragma unroll
    for (int mi = 0; mi < 2; ++mi) {
#pragma unroll
        for (int ni = 0; ni < 8; ++ni) {
            const int r0 = bm + wm * 32 + mi * 16 + (lane >> 2);
            const int c0 = bn + wn * 64 + ni * 8 + (lane & 3) * 2;
            const float b0 = bias[c0];
            const float b1 = bias[c0 + 1];
            float2 v01 = make_float2(acc[mi][ni][0] + b0, acc[mi][ni][1] + b1);
            float2 v23 = make_float2(acc[mi][ni][2] + b0, acc[mi][ni][3] + b1);
            if (!QKV) {
                *(float2*)&C[(size_t)r0 * N_ + c0] = v01;
                *(float2*)&C[(size_t)(r0 + 8) * N_ + c0] = v23;
            } else {
                __half* dst = (wsel == 0) ? g_qf : (wsel == 1) ? g_kf : g_vf;
                const int h = c0 >> 6;
                const int d = c0 & (DK_ - 1);
#pragma unroll
                for (int rr = 0; rr < 2; ++rr) {
                    const int row = r0 + rr * 8;
                    const int b = row >> 11, t = row & (T_ - 1);
                    const float x0 = rr ? v23.x : v01.x;
                    const float x1 = rr ? v23.y : v01.y;
                    size_t off = (((size_t)b * H_ + h) * T_ + t) * DK_ + d;
                    *(__half2*)&dst[off] = __floats2half2_rn(x0, x1);
                }
            }
        }
    }
}

// ---------------------------------------------------------------------------
// Flash attention: single fp16 QK^T and PV, depth-2 fragment prefetch.
// Causal, online softmax. 128 threads, 64 query rows. 2 CTAs/SM.
// ---------------------------------------------------------------------------
constexpr int AT_STRIDE = 72;
constexpr int AT_TILE = 64 * AT_STRIDE;
constexpr int AT_KVBASE = AT_TILE;                          // after Qf
constexpr int AT_STAGE = 2 * AT_TILE;                       // Kf,Vf
constexpr int AT_SMEM_ELEMS = AT_KVBASE + 2 * AT_STAGE;     // 23040
constexpr int AT_SMEM_BYTES = AT_SMEM_ELEMS * 2;            // 46080

__device__ __forceinline__ void at_load_kv(uint32_t sb, int stage, size_t gbase, int kt, int tid)
{
    uint32_t stbase = sb + (AT_KVBASE + stage * AT_STAGE) * 2;
    const __half* srcs[2] = {g_kf, g_vf};
#pragma unroll
    for (int i = 0; i < 8; ++i) {
        const int arr = i >> 2;
        const int within = (tid + (i & 3) * 128) & 511;
        const int row = within >> 3;
        const int cc = within & 7;
        uint32_t so = stbase + (arr * AT_TILE + row * AT_STRIDE + cc * 8) * 2;
        cp16(so, srcs[arr] + gbase + (size_t)(kt * 64 + row) * DK_ + cc * 8);
    }
    asm volatile("cp.async.commit_group;\n" ::);
}

__global__ __launch_bounds__(128, 2)
void attn_kernel()
{
    extern __shared__ __half at_sm[];
    uint32_t sb = (uint32_t)__cvta_generic_to_shared(at_sm);

    const int tid = threadIdx.x;
    const int lane = tid & 31;
    const int warp = tid >> 5;

    const int qt = (int)gridDim.x - 1 - (int)blockIdx.x;
    const int bh = blockIdx.y;
    const size_t gbase = (size_t)bh * T_ * DK_;

#pragma unroll
    for (int i = 0; i < 4; ++i) {
        const int within = tid + i * 128;
        const int row = within >> 3;
        const int cc = within & 7;
        uint32_t so = sb + (row * AT_STRIDE + cc * 8) * 2;
        cp16(so, g_qf + gbase + (size_t)(qt * 64 + row) * DK_ + cc * 8);
    }
    at_load_kv(sb, 0, gbase, 0, tid);

    float oAcc[8][4];
#pragma unroll
    for (int nt = 0; nt < 8; ++nt)
#pragma unroll
        for (int c = 0; c < 4; ++c) oAcc[nt][c] = 0.0f;

    float m0 = -1e30f, m1 = -1e30f, l0 = 0.0f, l1 = 0.0f;
    const int row0g = qt * 64 + warp * 16 + (lane >> 2);

    uint32_t qf[4][4];
    bool qloaded = false;

#pragma unroll 1
    for (int kt = 0; kt <= qt; ++kt) {
        const int s = kt & 1;
        asm volatile("cp.async.wait_group 0;\n" ::);
        __syncthreads();
        if (kt + 1 <= qt)
            at_load_kv(sb, s ^ 1, gbase, kt + 1, tid);

        if (!qloaded) {
            qloaded = true;
#pragma unroll
            for (int k16 = 0; k16 < 4; ++k16) {
                int row = warp * 16 + (lane & 15);
                uint32_t off = (uint32_t)(row * AT_STRIDE + (lane >> 4) * 8 + k16 * 16) * 2;
                ldsm4(qf[k16], sb + off);
            }
        }

        const uint32_t kvb = sb + (AT_KVBASE + s * AT_STAGE) * 2;

        // ---- S = Q @ K^T (flattened, depth-2 K-frag prefetch) ----
        float sAcc[8][4];
#pragma unroll
        for (int nt = 0; nt < 8; ++nt)
#pragma unroll
            for (int c = 0; c < 4; ++c) sAcc[nt][c] = 0.0f;

        const int krow0 = (lane & 7) + ((lane >> 4) << 3);
        const uint32_t kcol = ((lane >> 3) & 1) * 8;
        auto kaddr = [&](int it) -> uint32_t {
            const int k16 = it >> 2, np = it & 3;
            return kvb + (uint32_t)((np * 16 + krow0) * AT_STRIDE + kcol + k16 * 16) * 2;
        };
        {
            uint32_t kfb[3][4];
            ldsm4(kfb[0], kaddr(0));
            ldsm4(kfb[1], kaddr(1));
#pragma unroll
            for (int it = 0; it < 16; ++it) {
                if (it + 2 < 16) ldsm4(kfb[(it + 2) % 3], kaddr(it + 2));
                const int k16 = it >> 2, np = it & 3;
                const uint32_t* kf = kfb[it % 3];
                mma16816f(sAcc[np * 2],     qf[k16], kf);
                mma16816f(sAcc[np * 2 + 1], qf[k16], kf + 2);
            }
        }

        // ---- scale + causal mask ----
        const float invs = 0.125f;
        if (kt == qt) {
#pragma unroll
            for (int nt = 0; nt < 8; ++nt) {
                const int colb = kt * 64 + nt * 8 + (lane & 3) * 2;
#pragma unroll
                for (int c = 0; c < 4; ++c) {
                    const int col = colb + (c & 1);
                    const int row = row0g + ((c >> 1) << 3);
                    sAcc[nt][c] = (col <= row) ? sAcc[nt][c] * invs : -1e30f;
                }
            }
        } else {
#pragma unroll
            for (int nt = 0; nt < 8; ++nt)
#pragma unroll
                for (int c = 0; c < 4; ++c) sAcc[nt][c] *= invs;
        }

        // ---- online softmax ----
        float mx0 = -1e30f, mx1 = -1e30f;
#pragma unroll
        for (int nt = 0; nt < 8; ++nt) {
            mx0 = fmaxf(mx0, fmaxf(sAcc[nt][0], sAcc[nt][1]));
            mx1 = fmaxf(mx1, fmaxf(sAcc[nt][2], sAcc[nt][3]));
        }
        mx0 = fmaxf(mx0, __shfl_xor_sync(0xffffffffu, mx0, 1));
        mx0 = fmaxf(mx0, __shfl_xor_sync(0xffffffffu, mx0, 2));
        mx1 = fmaxf(mx1, __shfl_xor_sync(0xffffffffu, mx1, 1));
        mx1 = fmaxf(mx1, __shfl_xor_sync(0xffffffffu, mx1, 2));

        const float mn0 = fmaxf(m0, mx0);
        const float mn1 = fmaxf(m1, mx1);
        const float fac0 = fexp(m0 - mn0);
        const float fac1 = fexp(m1 - mn1);
        m0 = mn0; m1 = mn1;

        float sum0 = 0.0f, sum1 = 0.0f;
#pragma unroll
        for (int nt = 0; nt < 8; ++nt) {
            sAcc[nt][0] = fexp(sAcc[nt][0] - m0);
            sAcc[nt][1] = fexp(sAcc[nt][1] - m0);
            sAcc[nt][2] = fexp(sAcc[nt][2] - m1);
            sAcc[nt][3] = fexp(sAcc[nt][3] - m1);
            sum0 += sAcc[nt][0] + sAcc[nt][1];
            sum1 += sAcc[nt][2] + sAcc[nt][3];
        }
        sum0 += __shfl_xor_sync(0xffffffffu, sum0, 1);
        sum0 += __shfl_xor_sync(0xffffffffu, sum0, 2);
        sum1 += __shfl_xor_sync(0xffffffffu, sum1, 1);
        sum1 += __shfl_xor_sync(0xffffffffu, sum1, 2);
        l0 = l0 * fac0 + sum0;
        l1 = l1 * fac1 + sum1;

#pragma unroll
        for (int nt = 0; nt < 8; ++nt) {
            oAcc[nt][0] *= fac0; oAcc[nt][1] *= fac0;
            oAcc[nt][2] *= fac1; oAcc[nt][3] *= fac1;
        }

        // ---- O += P @ V (flattened, depth-2 V-frag prefetch) ----
        const uint32_t vb = kvb + AT_TILE * 2;
        const int vrow0 = (lane & 7) + 8 * ((lane >> 3) & 1);
        const int vcol0 = 8 * (lane >> 4);
        auto vaddr = [&](int it) -> uint32_t {
            const int c16 = it >> 2, np = it & 3;
            return vb + (uint32_t)((c16 * 16 + vrow0) * AT_STRIDE + np * 16 + vcol0) * 2;
        };
        {
            uint32_t vfb[3][4];
            uint32_t pa[4];
            ldsm4t(vfb[0], vaddr(0));
            ldsm4t(vfb[1], vaddr(1));
#pragma unroll
            for (int it = 0; it < 16; ++it) {
                if (it + 2 < 16) ldsm4t(vfb[(it + 2) % 3], vaddr(it + 2));
                const int c16 = it >> 2, np = it & 3;
                if (np == 0) {
#pragma unroll
                    for (int half = 0; half < 2; ++half) {
                        const float* pv = sAcc[2 * c16 + half];
                        __half2 p01 = __floats2half2_rn(pv[0], pv[1]);
                        __half2 p23 = __floats2half2_rn(pv[2], pv[3]);
                        pa[half * 2 + 0] = *(uint32_t*)&p01;
                        pa[half * 2 + 1] = *(uint32_t*)&p23;
                    }
                }
                const uint32_t* vf = vfb[it % 3];
                mma16816f(oAcc[np * 2],     pa, vf);
                mma16816f(oAcc[np * 2 + 1], pa, vf + 2);
            }
        }
    }

    // ---- epilogue ----
    const float inv0 = 1.0f / l0;
    const float inv1 = 1.0f / l1;
    const int b = bh >> 4;
    const int h = bh & 15;
#pragma unroll
    for (int rr = 0; rr < 2; ++rr) {
        const int t = qt * 64 + warp * 16 + (lane >> 2) + rr * 8;
        const float inv = rr ? inv1 : inv0;
        size_t rowoff = AOFF + ((size_t)b * T_ + t) * D_ + h * DK_ + (lane & 3) * 2;
#pragma unroll
        for (int nt = 0; nt < 8; ++nt) {
            *(__half2*)&g_af[rowoff + nt * 8] = __floats2half2_rn(
                oAcc[nt][rr * 2] * inv, oAcc[nt][rr * 2 + 1] * inv);
        }
    }
}

// ---------------------------------------------------------------------------
// Launch
// ---------------------------------------------------------------------------
extern "C" void kernel_launch(void* const* d_in, const int* in_sizes, int n_in,
                              void* d_out, int out_size)
{
    (void)in_sizes; (void)n_in; (void)out_size;
    const float* x  = (const float*)d_in[0];
    const float* Wq = (const float*)d_in[2];
    const float* Wk = (const float*)d_in[3];
    const float* Wv = (const float*)d_in[4];
    const float* Wo = (const float*)d_in[5];
    const float* bq = (const float*)d_in[6];
    const float* bk = (const float*)d_in[7];
    const float* bv = (const float*)d_in[8];
    const float* bo = (const float*)d_in[9];
    float* out = (float*)d_out;

    conv_all<<<NBX + 4 * NBW, 256>>>(x, Wq, Wk, Wv, Wo);

    const int gemm_smem = G_NSTG * STAGE_B;   // 61440
    cudaFuncSetAttribute(mma_gemm<1>, cudaFuncAttributeMaxDynamicSharedMemorySize, gemm_smem);
    cudaFuncSetAttribute(mma_gemm<0>, cudaFuncAttributeMaxDynamicSharedMemorySize, gemm_smem);
    cudaFuncSetAttribute(attn_kernel, cudaFuncAttributeMaxDynamicSharedMemorySize, AT_SMEM_BYTES);

    // Fused QKV projection: grid (3*8, 64)
    mma_gemm<1><<<dim3(24, M_ / 128), 256, gemm_smem>>>(bq, bk, bv, nullptr);

    // Attention: 64 query rows per CTA, 2 CTAs/SM
    attn_kernel<<<dim3(T_ / 64, B_ * H_), 128, AT_SMEM_BYTES>>>();

    // Output projection
    mma_gemm<0><<<dim3(N_ / 128, M_ / 128), 256, gemm_smem>>>(bo, nullptr, nullptr, out);
}